// round 3
// baseline (speedup 1.0000x reference)
#include <cuda_runtime.h>
#include <math.h>

#define CB 2
#define CS 2048
#define CE 1024
#define CH 16
#define CD 64
#define CM (CB*CS)          // 4096 tokens
#define YAT_EPS 1e-5f

typedef unsigned long long u64;

// ---- packed f32x2 helpers (sm_103a FFMA2 path; ptxas won't auto-fuse) ----
__device__ __forceinline__ void ffma2(u64 &d, u64 a, u64 b) {
    asm("fma.rn.f32x2 %0, %1, %2, %0;" : "+l"(d) : "l"(a), "l"(b));
}
__device__ __forceinline__ u64 mul2(u64 a, u64 b) {
    u64 r; asm("mul.rn.f32x2 %0, %1, %2;" : "=l"(r) : "l"(a), "l"(b)); return r;
}
__device__ __forceinline__ u64 pk2(float x, float y) {
    u64 r; asm("mov.b64 %0, {%1, %2};" : "=l"(r) : "f"(x), "f"(y)); return r;
}
__device__ __forceinline__ u64 dup2(float x) {
    u64 r; asm("mov.b64 %0, {%1, %1};" : "=l"(r) : "f"(x)); return r;
}
__device__ __forceinline__ float2 unpk(u64 v) {
    float2 f; asm("mov.b64 {%0, %1}, %2;" : "=f"(f.x), "=f"(f.y) : "l"(v)); return f;
}

// Scratch (allocation-free rule: __device__ globals)
__device__ float g_q[(size_t)CM*CE];
__device__ float g_k[(size_t)CM*CE];
__device__ float g_v[(size_t)CM*CE];
__device__ float g_o[(size_t)CM*CE];

// ---------------------------------------------------------------------------
// C[M,N] = A[M,K] @ B[N,K]^T + bias[N]   (nn.Linear: x @ W.T + b)
// 128x128 tile, BK=16, 256 threads, 8x8 per thread, FFMA2 inner loop.
// ---------------------------------------------------------------------------
__global__ __launch_bounds__(256) void gemm_nt_bias(
    const float* __restrict__ A, const float* __restrict__ B,
    const float* __restrict__ bias, float* __restrict__ C,
    int M, int N, int K)
{
    const int BM = 128, BN = 128, BK = 16;
    __shared__ float As[BK][BM + 4];
    __shared__ float Bs[BK][BN + 4];

    const int tid = threadIdx.x;
    const int tx = tid & 15;         // 0..15 (cols)
    const int ty = tid >> 4;         // 0..15 (rows)
    const int row0 = blockIdx.y * BM;
    const int col0 = blockIdx.x * BN;

    u64 accp[8][4];
#pragma unroll
    for (int i = 0; i < 8; i++)
#pragma unroll
        for (int j = 0; j < 4; j++) accp[i][j] = 0ull;

    const int lr = tid >> 2;           // 0..63
    const int lc = (tid & 3) << 2;     // 0,4,8,12
    const float* Ab = A + (size_t)row0 * K;
    const float* Bb = B + (size_t)col0 * K;

    for (int k0 = 0; k0 < K; k0 += BK) {
#pragma unroll
        for (int rr = 0; rr < 2; rr++) {
            int r = lr + rr * 64;
            float4 va = *(const float4*)&Ab[(size_t)r * K + k0 + lc];
            As[lc + 0][r] = va.x; As[lc + 1][r] = va.y;
            As[lc + 2][r] = va.z; As[lc + 3][r] = va.w;
            float4 vb = *(const float4*)&Bb[(size_t)r * K + k0 + lc];
            Bs[lc + 0][r] = vb.x; Bs[lc + 1][r] = vb.y;
            Bs[lc + 2][r] = vb.z; Bs[lc + 3][r] = vb.w;
        }
        __syncthreads();
#pragma unroll
        for (int k = 0; k < BK; k++) {
            float4 a0 = *(const float4*)&As[k][ty * 8];
            float4 a1 = *(const float4*)&As[k][ty * 8 + 4];
            float4 b0 = *(const float4*)&Bs[k][tx * 8];
            float4 b1 = *(const float4*)&Bs[k][tx * 8 + 4];
            u64 rb[4];
            rb[0] = pk2(b0.x, b0.y); rb[1] = pk2(b0.z, b0.w);
            rb[2] = pk2(b1.x, b1.y); rb[3] = pk2(b1.z, b1.w);
            float ra[8] = {a0.x, a0.y, a0.z, a0.w, a1.x, a1.y, a1.z, a1.w};
#pragma unroll
            for (int i = 0; i < 8; i++) {
                u64 ad = dup2(ra[i]);
#pragma unroll
                for (int j = 0; j < 4; j++)
                    ffma2(accp[i][j], ad, rb[j]);
            }
        }
        __syncthreads();
    }

#pragma unroll
    for (int i = 0; i < 8; i++) {
        size_t r = (size_t)(row0 + ty * 8 + i);
#pragma unroll
        for (int j0 = 0; j0 < 2; j0++) {
            int c = col0 + tx * 8 + j0 * 4;
            float2 p0 = unpk(accp[i][j0 * 2 + 0]);
            float2 p1 = unpk(accp[i][j0 * 2 + 1]);
            float4 o;
            o.x = p0.x + bias[c + 0];
            o.y = p0.y + bias[c + 1];
            o.z = p1.x + bias[c + 2];
            o.w = p1.y + bias[c + 3];
            *(float4*)&C[r * N + c] = o;
        }
    }
}

// ---------------------------------------------------------------------------
// Fused YAT attention, flash-style online softmax, FFMA2 inner loops.
// Grid: (S/64, H, B). Block: 256 threads (16x16). 64x64 q/kv tiles.
// ---------------------------------------------------------------------------
__global__ __launch_bounds__(256) void yat_attention(
    const float* __restrict__ Qm, const float* __restrict__ Km,
    const float* __restrict__ Vm, float* __restrict__ Om,
    const float* __restrict__ alphap)
{
    extern __shared__ float sm[];
    float* Qst = sm;               // 64*64  (d-major)
    float* Kst = sm + 4096;        // 64*64  (d-major)
    float* Vs  = sm + 8192;        // 64*64  (kv-major)
    float* Ps  = sm + 12288;       // 64*68  (kv-major, padded)

    const int tid = threadIdx.x;
    const int tx = tid & 15;       // kv-col group / d group
    const int ty = tid >> 4;       // q-row group
    const int b = blockIdx.z, h = blockIdx.y;
    const int q0 = blockIdx.x * 64;

    const float scale = powf(8.0f / logf(65.0f), alphap[0]);  // (sqrt(D)/log1p(D))^alpha

    // Load Q tile transposed: Qst[d][r]
    {
        int r = tid >> 2;
        int d0 = (tid & 3) << 4;
        const float* qp = &Qm[((size_t)(b * CS + q0 + r)) * CE + h * CD + d0];
#pragma unroll
        for (int u = 0; u < 4; u++) {
            float4 v = *(const float4*)(qp + u * 4);
            Qst[(d0 + u * 4 + 0) * 64 + r] = v.x;
            Qst[(d0 + u * 4 + 1) * 64 + r] = v.y;
            Qst[(d0 + u * 4 + 2) * 64 + r] = v.z;
            Qst[(d0 + u * 4 + 3) * 64 + r] = v.w;
        }
    }
    __syncthreads();

    // ||q||^2 for this thread's 4 rows
    float sqr[4] = {0.f, 0.f, 0.f, 0.f};
#pragma unroll 16
    for (int d = 0; d < 64; d++) {
        float4 qv = *(const float4*)&Qst[d * 64 + ty * 4];
        sqr[0] += qv.x * qv.x; sqr[1] += qv.y * qv.y;
        sqr[2] += qv.z * qv.z; sqr[3] += qv.w * qv.w;
    }

    float mrow[4], lrow[4];
    u64 accO2[4][2];
#pragma unroll
    for (int i = 0; i < 4; i++) {
        mrow[i] = -INFINITY; lrow[i] = 0.0f;
        accO2[i][0] = 0ull; accO2[i][1] = 0ull;
    }

    for (int t = 0; t < CS / 64; t++) {
        __syncthreads();   // protect Kst/Vs/Ps against previous iteration's readers
        {
            int r = tid >> 2;
            int d0 = (tid & 3) << 4;
            const float* kp = &Km[((size_t)(b * CS + t * 64 + r)) * CE + h * CD + d0];
            const float* vp = &Vm[((size_t)(b * CS + t * 64 + r)) * CE + h * CD + d0];
#pragma unroll
            for (int u = 0; u < 4; u++) {
                float4 kv = *(const float4*)(kp + u * 4);
                Kst[(d0 + u * 4 + 0) * 64 + r] = kv.x;
                Kst[(d0 + u * 4 + 1) * 64 + r] = kv.y;
                Kst[(d0 + u * 4 + 2) * 64 + r] = kv.z;
                Kst[(d0 + u * 4 + 3) * 64 + r] = kv.w;
                *(float4*)&Vs[r * 64 + d0 + u * 4] = *(const float4*)(vp + u * 4);
            }
        }
        __syncthreads();

        // S = Q K^T (packed f32x2, ||k||^2 fused into the same d-loop)
        u64 accS2[4][2];
        u64 skc2[2];
#pragma unroll
        for (int i = 0; i < 4; i++) { accS2[i][0] = 0ull; accS2[i][1] = 0ull; }
        skc2[0] = 0ull; skc2[1] = 0ull;

#pragma unroll 8
        for (int d = 0; d < 64; d++) {
            float4 qv = *(const float4*)&Qst[d * 64 + ty * 4];
            float4 kv = *(const float4*)&Kst[d * 64 + tx * 4];
            u64 k0 = pk2(kv.x, kv.y);
            u64 k1 = pk2(kv.z, kv.w);
            ffma2(skc2[0], k0, k0);
            ffma2(skc2[1], k1, k1);
            float qa[4] = {qv.x, qv.y, qv.z, qv.w};
#pragma unroll
            for (int i = 0; i < 4; i++) {
                u64 qq = dup2(qa[i]);
                ffma2(accS2[i][0], qq, k0);
                ffma2(accS2[i][1], qq, k1);
            }
        }

        float2 kcA = unpk(skc2[0]), kcB = unpk(skc2[1]);
        float kcs[4] = {kcA.x, kcA.y, kcB.x, kcB.y};

        // YAT score + online softmax (row groups of 16 lanes, xor-shfl reductions)
#pragma unroll
        for (int i = 0; i < 4; i++) {
            float2 sA = unpk(accS2[i][0]), sB = unpk(accS2[i][1]);
            float qk[4] = {sA.x, sA.y, sB.x, sB.y};
            float s[4];
            float mx = -INFINITY;
#pragma unroll
            for (int j = 0; j < 4; j++) {
                float dist = sqr[i] + kcs[j] - 2.0f * qk[j] + YAT_EPS;
                s[j] = scale * qk[j] * qk[j] / dist;
                mx = fmaxf(mx, s[j]);
            }
#pragma unroll
            for (int off = 8; off; off >>= 1)
                mx = fmaxf(mx, __shfl_xor_sync(0xffffffffu, mx, off));
            float mnew = fmaxf(mrow[i], mx);
            float corr = __expf(mrow[i] - mnew);
            mrow[i] = mnew;
            float rs = 0.0f;
#pragma unroll
            for (int j = 0; j < 4; j++) {
                s[j] = __expf(s[j] - mnew);
                rs += s[j];
            }
#pragma unroll
            for (int off = 8; off; off >>= 1)
                rs += __shfl_xor_sync(0xffffffffu, rs, off);
            lrow[i] = lrow[i] * corr + rs;
            u64 c2 = dup2(corr);
            accO2[i][0] = mul2(accO2[i][0], c2);
            accO2[i][1] = mul2(accO2[i][1], c2);
            // stash P transposed: Ps[kv][qrow]
#pragma unroll
            for (int j = 0; j < 4; j++)
                Ps[(tx * 4 + j) * 68 + ty * 4 + i] = s[j];
        }
        __syncthreads();

        // O += P @ V  (packed f32x2)
#pragma unroll 8
        for (int j = 0; j < 64; j++) {
            float4 pv = *(const float4*)&Ps[j * 68 + ty * 4];
            float4 vv = *(const float4*)&Vs[j * 64 + tx * 4];
            u64 v0 = pk2(vv.x, vv.y);
            u64 v1 = pk2(vv.z, vv.w);
            float pa[4] = {pv.x, pv.y, pv.z, pv.w};
#pragma unroll
            for (int i = 0; i < 4; i++) {
                u64 pp = dup2(pa[i]);
                ffma2(accO2[i][0], pp, v0);
                ffma2(accO2[i][1], pp, v1);
            }
        }
    }

    // epilogue: divide by row sum, write [B,S,H,D]
#pragma unroll
    for (int i = 0; i < 4; i++) {
        float inv = 1.0f / lrow[i];
        float2 oa = unpk(accO2[i][0]);
        float2 ob = unpk(accO2[i][1]);
        float4 o;
        o.x = oa.x * inv; o.y = oa.y * inv;
        o.z = ob.x * inv; o.w = ob.y * inv;
        *(float4*)&Om[((size_t)(b * CS + q0 + ty * 4 + i)) * CE + h * CD + tx * 4] = o;
    }
}

// ---------------------------------------------------------------------------
extern "C" void kernel_launch(void* const* d_in, const int* in_sizes, int n_in,
                              void* d_out, int out_size)
{
    (void)in_sizes; (void)n_in; (void)out_size;
    const float* query = (const float*)d_in[0];
    const float* Wq    = (const float*)d_in[1];
    const float* bq    = (const float*)d_in[2];
    const float* Wk    = (const float*)d_in[3];
    const float* bk    = (const float*)d_in[4];
    const float* Wv    = (const float*)d_in[5];
    const float* bv    = (const float*)d_in[6];
    const float* Wo    = (const float*)d_in[7];
    const float* bo    = (const float*)d_in[8];
    const float* alpha = (const float*)d_in[9];

    float *q, *k, *v, *o;
    cudaGetSymbolAddress((void**)&q, g_q);
    cudaGetSymbolAddress((void**)&k, g_k);
    cudaGetSymbolAddress((void**)&v, g_v);
    cudaGetSymbolAddress((void**)&o, g_o);

    dim3 gg(CE / 128, CM / 128);   // (8, 32)
    gemm_nt_bias<<<gg, 256>>>(query, Wq, bq, q, CM, CE, CE);
    gemm_nt_bias<<<gg, 256>>>(query, Wk, bk, k, CM, CE, CE);
    gemm_nt_bias<<<gg, 256>>>(query, Wv, bv, v, CM, CE, CE);

    const size_t smem = (3 * 4096 + 64 * 68) * sizeof(float);   // 66560 B
    cudaFuncSetAttribute(yat_attention, cudaFuncAttributeMaxDynamicSharedMemorySize, (int)smem);
    yat_attention<<<dim3(CS / 64, CH, CB), 256, smem>>>(q, k, v, o, alpha);

    gemm_nt_bias<<<gg, 256>>>(o, Wo, bo, (float*)d_out, CM, CE, CE);
}

// round 5
// speedup vs baseline: 1.3334x; 1.3334x over previous
#include <cuda_runtime.h>
#include <cuda_bf16.h>
#include <math.h>
#include <stdint.h>

#define CB 2
#define CS 2048
#define CE 1024
#define CH 16
#define CD 64
#define CM (CB*CS)          // 4096 tokens
#define YAT_EPS 1e-5f

typedef unsigned long long u64;

// ---- packed f32x2 helpers ----
__device__ __forceinline__ void ffma2(u64 &d, u64 a, u64 b) {
    asm("fma.rn.f32x2 %0, %1, %2, %0;" : "+l"(d) : "l"(a), "l"(b));
}
__device__ __forceinline__ u64 mul2(u64 a, u64 b) {
    u64 r; asm("mul.rn.f32x2 %0, %1, %2;" : "=l"(r) : "l"(a), "l"(b)); return r;
}
__device__ __forceinline__ u64 pk2(float x, float y) {
    u64 r; asm("mov.b64 %0, {%1, %2};" : "=l"(r) : "f"(x), "f"(y)); return r;
}
__device__ __forceinline__ u64 dup2(float x) {
    u64 r; asm("mov.b64 %0, {%1, %1};" : "=l"(r) : "f"(x)); return r;
}
__device__ __forceinline__ float2 unpk(u64 v) {
    float2 f; asm("mov.b64 {%0, %1}, %2;" : "=f"(f.x), "=f"(f.y) : "l"(v)); return f;
}

__device__ __forceinline__ uint32_t smem_u32(const void* p) {
    uint32_t a;
    asm("{ .reg .u64 t; cvta.to.shared.u64 t, %1; cvt.u32.u64 %0, t; }" : "=r"(a) : "l"(p));
    return a;
}

// ---- mma.sync / ldmatrix helpers (portable to non-'a' sm_103 target) ----
__device__ __forceinline__ void ldsm_x4(uint32_t* r, uint32_t addr) {
    asm volatile("ldmatrix.sync.aligned.m8n8.x4.shared.b16 {%0,%1,%2,%3}, [%4];"
        : "=r"(r[0]), "=r"(r[1]), "=r"(r[2]), "=r"(r[3]) : "r"(addr));
}
__device__ __forceinline__ void mma_bf16(float* c, const uint32_t* a, const uint32_t* b) {
    asm volatile(
        "mma.sync.aligned.m16n8k16.row.col.f32.bf16.bf16.f32 "
        "{%0,%1,%2,%3}, {%4,%5,%6,%7}, {%8,%9}, {%0,%1,%2,%3};"
        : "+f"(c[0]), "+f"(c[1]), "+f"(c[2]), "+f"(c[3])
        : "r"(a[0]), "r"(a[1]), "r"(a[2]), "r"(a[3]), "r"(b[0]), "r"(b[1]));
}

// ---- Scratch (__device__ globals; allocation-free rule) ----
__device__ float g_q[(size_t)CM*CE];
__device__ float g_k[(size_t)CM*CE];
__device__ float g_v[(size_t)CM*CE];
__device__ float g_o[(size_t)CM*CE];
__device__ __nv_bfloat16 g_xh[(size_t)CM*CE], g_xl[(size_t)CM*CE];   // query split
__device__ __nv_bfloat16 g_oh[(size_t)CM*CE], g_ol[(size_t)CM*CE];   // attn out split
__device__ __nv_bfloat16 g_wqh[(size_t)CE*CE], g_wql[(size_t)CE*CE];
__device__ __nv_bfloat16 g_wkh[(size_t)CE*CE], g_wkl[(size_t)CE*CE];
__device__ __nv_bfloat16 g_wvh[(size_t)CE*CE], g_wvl[(size_t)CE*CE];
__device__ __nv_bfloat16 g_woh[(size_t)CE*CE], g_wol[(size_t)CE*CE];

// ---------------------------------------------------------------------------
// fp32 -> (bf16 hi, bf16 lo) split, vectorized
// ---------------------------------------------------------------------------
__global__ __launch_bounds__(256) void split_bf16(
    const float* __restrict__ x, __nv_bfloat16* __restrict__ hi,
    __nv_bfloat16* __restrict__ lo, int n4)
{
    int i = blockIdx.x * blockDim.x + threadIdx.x;
    if (i >= n4) return;
    float4 v = ((const float4*)x)[i];
    union { __nv_bfloat16 b[4]; uint2 u; } H, L;
    float a[4] = {v.x, v.y, v.z, v.w};
#pragma unroll
    for (int j = 0; j < 4; j++) {
        __nv_bfloat16 h = __float2bfloat16(a[j]);
        H.b[j] = h;
        L.b[j] = __float2bfloat16(a[j] - __bfloat162float(h));
    }
    ((uint2*)hi)[i] = H.u;
    ((uint2*)lo)[i] = L.u;
}

// ---------------------------------------------------------------------------
// C[M,N] = A[M,K] @ B[N,K]^T + bias via mma.sync bf16 3-split (HMMA path).
// 128x128 CTA tile, BK=32, 256 threads = 8 warps in 2x4 grid, 64x32 per warp.
// smem rows padded to 40 bf16 (80B) to spread ldmatrix banks.
// ---------------------------------------------------------------------------
#define LDA 40
__global__ __launch_bounds__(256) void hgemm_nt_3split(
    const __nv_bfloat16* __restrict__ Ah, const __nv_bfloat16* __restrict__ Al,
    const __nv_bfloat16* __restrict__ Bh, const __nv_bfloat16* __restrict__ Bl,
    const float* __restrict__ bias, float* __restrict__ C,
    int M, int N, int K)
{
    __shared__ __nv_bfloat16 sAh[128 * LDA], sAl[128 * LDA];
    __shared__ __nv_bfloat16 sBh[128 * LDA], sBl[128 * LDA];

    const int tid = threadIdx.x, lane = tid & 31, wid = tid >> 5;
    const int wm = wid >> 2, wn = wid & 3;          // 2 x 4 warp grid
    const int row0 = blockIdx.y * 128, col0 = blockIdx.x * 128;

    const uint32_t uAh = smem_u32(sAh), uAl = smem_u32(sAl);
    const uint32_t uBh = smem_u32(sBh), uBl = smem_u32(sBl);

    float acc[4][4][4];
#pragma unroll
    for (int i = 0; i < 4; i++)
#pragma unroll
        for (int j = 0; j < 4; j++)
#pragma unroll
            for (int f = 0; f < 4; f++) acc[i][j][f] = 0.0f;

    // ldmatrix per-thread addressing (element offsets)
    const int a_row = lane & 15, a_kg = lane >> 4;               // A: mats m0-7/k0, m8-15/k0, m0-7/k8, m8-15/k8
    const int b_row = ((lane >> 4) & 1) * 8 + (lane & 7);        // B: mats n0-7/k0, n0-7/k8, n8-15/k0, n8-15/k8
    const int b_kg  = (lane >> 3) & 1;

    const int gr = tid >> 2;                 // 0..63 (global load row)
    const int gc = (tid & 3) * 8;            // 0,8,16,24

    for (int k0 = 0; k0 < K; k0 += 32) {
        __syncthreads();
#pragma unroll
        for (int pp = 0; pp < 2; pp++) {
            int r = pp * 64 + gr;
            size_t ga = (size_t)(row0 + r) * K + k0 + gc;
            size_t gb = (size_t)(col0 + r) * K + k0 + gc;
            *(uint4*)&sAh[r * LDA + gc] = *(const uint4*)&Ah[ga];
            *(uint4*)&sAl[r * LDA + gc] = *(const uint4*)&Al[ga];
            *(uint4*)&sBh[r * LDA + gc] = *(const uint4*)&Bh[gb];
            *(uint4*)&sBl[r * LDA + gc] = *(const uint4*)&Bl[gb];
        }
        __syncthreads();

#pragma unroll
        for (int kk = 0; kk < 2; kk++) {
            const uint32_t aoff = ((wm * 64 + a_row) * LDA + kk * 16 + a_kg * 8) * 2;
            const uint32_t boff0 = ((wn * 32 + b_row) * LDA + kk * 16 + b_kg * 8) * 2;
            const uint32_t boff1 = boff0 + 16 * LDA * 2;

            uint32_t bh_f[4][2], bl_f[4][2], af[4][4];
            {
                uint32_t t[4];
                ldsm_x4(t, uBh + boff0);
                bh_f[0][0] = t[0]; bh_f[0][1] = t[1]; bh_f[1][0] = t[2]; bh_f[1][1] = t[3];
                ldsm_x4(t, uBh + boff1);
                bh_f[2][0] = t[0]; bh_f[2][1] = t[1]; bh_f[3][0] = t[2]; bh_f[3][1] = t[3];
                ldsm_x4(t, uBl + boff0);
                bl_f[0][0] = t[0]; bl_f[0][1] = t[1]; bl_f[1][0] = t[2]; bl_f[1][1] = t[3];
                ldsm_x4(t, uBl + boff1);
                bl_f[2][0] = t[0]; bl_f[2][1] = t[1]; bl_f[3][0] = t[2]; bl_f[3][1] = t[3];
            }
            // A-high frags: Ah*Bh and Ah*Bl
#pragma unroll
            for (int mi = 0; mi < 4; mi++)
                ldsm_x4(af[mi], uAh + aoff + mi * 16 * LDA * 2);
#pragma unroll
            for (int mi = 0; mi < 4; mi++)
#pragma unroll
                for (int ni = 0; ni < 4; ni++) {
                    mma_bf16(acc[mi][ni], af[mi], bh_f[ni]);
                    mma_bf16(acc[mi][ni], af[mi], bl_f[ni]);
                }
            // A-low frags (reuse af): Al*Bh
#pragma unroll
            for (int mi = 0; mi < 4; mi++)
                ldsm_x4(af[mi], uAl + aoff + mi * 16 * LDA * 2);
#pragma unroll
            for (int mi = 0; mi < 4; mi++)
#pragma unroll
                for (int ni = 0; ni < 4; ni++)
                    mma_bf16(acc[mi][ni], af[mi], bh_f[ni]);
        }
    }

    // epilogue: c0,c1 -> (row, col..col+1); c2,c3 -> (row+8, ...)
    const int erow = lane >> 2, ecol = (lane & 3) * 2;
#pragma unroll
    for (int mi = 0; mi < 4; mi++) {
#pragma unroll
        for (int ni = 0; ni < 4; ni++) {
            int rg = row0 + wm * 64 + mi * 16 + erow;
            int cg = col0 + wn * 32 + ni * 8 + ecol;
            float2 bb = *(const float2*)&bias[cg];
            float2 o0 = {acc[mi][ni][0] + bb.x, acc[mi][ni][1] + bb.y};
            float2 o1 = {acc[mi][ni][2] + bb.x, acc[mi][ni][3] + bb.y};
            *(float2*)&C[(size_t)rg * N + cg] = o0;
            *(float2*)&C[(size_t)(rg + 8) * N + cg] = o1;
        }
    }
}

// ---------------------------------------------------------------------------
// Fused YAT attention (unchanged): flash-style online softmax, FFMA2.
// ---------------------------------------------------------------------------
__global__ __launch_bounds__(256) void yat_attention(
    const float* __restrict__ Qm, const float* __restrict__ Km,
    const float* __restrict__ Vm, float* __restrict__ Om,
    const float* __restrict__ alphap)
{
    extern __shared__ float sm[];
    float* Qst = sm;               // 64*64  (d-major)
    float* Kst = sm + 4096;        // 64*64  (d-major)
    float* Vs  = sm + 8192;        // 64*64  (kv-major)
    float* Ps  = sm + 12288;       // 64*68  (kv-major, padded)

    const int tid = threadIdx.x;
    const int tx = tid & 15;
    const int ty = tid >> 4;
    const int b = blockIdx.z, h = blockIdx.y;
    const int q0 = blockIdx.x * 64;

    const float scale = powf(8.0f / logf(65.0f), alphap[0]);

    {
        int r = tid >> 2;
        int d0 = (tid & 3) << 4;
        const float* qp = &Qm[((size_t)(b * CS + q0 + r)) * CE + h * CD + d0];
#pragma unroll
        for (int u = 0; u < 4; u++) {
            float4 v = *(const float4*)(qp + u * 4);
            Qst[(d0 + u * 4 + 0) * 64 + r] = v.x;
            Qst[(d0 + u * 4 + 1) * 64 + r] = v.y;
            Qst[(d0 + u * 4 + 2) * 64 + r] = v.z;
            Qst[(d0 + u * 4 + 3) * 64 + r] = v.w;
        }
    }
    __syncthreads();

    float sqr[4] = {0.f, 0.f, 0.f, 0.f};
#pragma unroll 16
    for (int d = 0; d < 64; d++) {
        float4 qv = *(const float4*)&Qst[d * 64 + ty * 4];
        sqr[0] += qv.x * qv.x; sqr[1] += qv.y * qv.y;
        sqr[2] += qv.z * qv.z; sqr[3] += qv.w * qv.w;
    }

    float mrow[4], lrow[4];
    u64 accO2[4][2];
#pragma unroll
    for (int i = 0; i < 4; i++) {
        mrow[i] = -INFINITY; lrow[i] = 0.0f;
        accO2[i][0] = 0ull; accO2[i][1] = 0ull;
    }

    for (int t = 0; t < CS / 64; t++) {
        __syncthreads();
        {
            int r = tid >> 2;
            int d0 = (tid & 3) << 4;
            const float* kp = &Km[((size_t)(b * CS + t * 64 + r)) * CE + h * CD + d0];
            const float* vp = &Vm[((size_t)(b * CS + t * 64 + r)) * CE + h * CD + d0];
#pragma unroll
            for (int u = 0; u < 4; u++) {
                float4 kv = *(const float4*)(kp + u * 4);
                Kst[(d0 + u * 4 + 0) * 64 + r] = kv.x;
                Kst[(d0 + u * 4 + 1) * 64 + r] = kv.y;
                Kst[(d0 + u * 4 + 2) * 64 + r] = kv.z;
                Kst[(d0 + u * 4 + 3) * 64 + r] = kv.w;
                *(float4*)&Vs[r * 64 + d0 + u * 4] = *(const float4*)(vp + u * 4);
            }
        }
        __syncthreads();

        u64 accS2[4][2];
        u64 skc2[2];
#pragma unroll
        for (int i = 0; i < 4; i++) { accS2[i][0] = 0ull; accS2[i][1] = 0ull; }
        skc2[0] = 0ull; skc2[1] = 0ull;

#pragma unroll 8
        for (int d = 0; d < 64; d++) {
            float4 qv = *(const float4*)&Qst[d * 64 + ty * 4];
            float4 kv = *(const float4*)&Kst[d * 64 + tx * 4];
            u64 k0 = pk2(kv.x, kv.y);
            u64 k1 = pk2(kv.z, kv.w);
            ffma2(skc2[0], k0, k0);
            ffma2(skc2[1], k1, k1);
            float qa[4] = {qv.x, qv.y, qv.z, qv.w};
#pragma unroll
            for (int i = 0; i < 4; i++) {
                u64 qq = dup2(qa[i]);
                ffma2(accS2[i][0], qq, k0);
                ffma2(accS2[i][1], qq, k1);
            }
        }

        float2 kcA = unpk(skc2[0]), kcB = unpk(skc2[1]);
        float kcs[4] = {kcA.x, kcA.y, kcB.x, kcB.y};

#pragma unroll
        for (int i = 0; i < 4; i++) {
            float2 sA = unpk(accS2[i][0]), sB = unpk(accS2[i][1]);
            float qk[4] = {sA.x, sA.y, sB.x, sB.y};
            float s[4];
            float mx = -INFINITY;
#pragma unroll
            for (int j = 0; j < 4; j++) {
                float dist = sqr[i] + kcs[j] - 2.0f * qk[j] + YAT_EPS;
                s[j] = scale * qk[j] * qk[j] / dist;
                mx = fmaxf(mx, s[j]);
            }
#pragma unroll
            for (int off = 8; off; off >>= 1)
                mx = fmaxf(mx, __shfl_xor_sync(0xffffffffu, mx, off));
            float mnew = fmaxf(mrow[i], mx);
            float corr = __expf(mrow[i] - mnew);
            mrow[i] = mnew;
            float rs = 0.0f;
#pragma unroll
            for (int j = 0; j < 4; j++) {
                s[j] = __expf(s[j] - mnew);
                rs += s[j];
            }
#pragma unroll
            for (int off = 8; off; off >>= 1)
                rs += __shfl_xor_sync(0xffffffffu, rs, off);
            lrow[i] = lrow[i] * corr + rs;
            u64 c2 = dup2(corr);
            accO2[i][0] = mul2(accO2[i][0], c2);
            accO2[i][1] = mul2(accO2[i][1], c2);
#pragma unroll
            for (int j = 0; j < 4; j++)
                Ps[(tx * 4 + j) * 68 + ty * 4 + i] = s[j];
        }
        __syncthreads();

#pragma unroll 8
        for (int j = 0; j < 64; j++) {
            float4 pv = *(const float4*)&Ps[j * 68 + ty * 4];
            float4 vv = *(const float4*)&Vs[j * 64 + tx * 4];
            u64 v0 = pk2(vv.x, vv.y);
            u64 v1 = pk2(vv.z, vv.w);
            float pa[4] = {pv.x, pv.y, pv.z, pv.w};
#pragma unroll
            for (int i = 0; i < 4; i++) {
                u64 pp = dup2(pa[i]);
                ffma2(accO2[i][0], pp, v0);
                ffma2(accO2[i][1], pp, v1);
            }
        }
    }

#pragma unroll
    for (int i = 0; i < 4; i++) {
        float inv = 1.0f / lrow[i];
        float2 oa = unpk(accO2[i][0]);
        float2 ob = unpk(accO2[i][1]);
        float4 o;
        o.x = oa.x * inv; o.y = oa.y * inv;
        o.z = ob.x * inv; o.w = ob.y * inv;
        *(float4*)&Om[((size_t)(b * CS + q0 + ty * 4 + i)) * CE + h * CD + tx * 4] = o;
    }
}

// ---------------------------------------------------------------------------
extern "C" void kernel_launch(void* const* d_in, const int* in_sizes, int n_in,
                              void* d_out, int out_size)
{
    (void)in_sizes; (void)n_in; (void)out_size;
    const float* query = (const float*)d_in[0];
    const float* Wq    = (const float*)d_in[1];
    const float* bq    = (const float*)d_in[2];
    const float* Wk    = (const float*)d_in[3];
    const float* bk    = (const float*)d_in[4];
    const float* Wv    = (const float*)d_in[5];
    const float* bv    = (const float*)d_in[6];
    const float* Wo    = (const float*)d_in[7];
    const float* bo    = (const float*)d_in[8];
    const float* alpha = (const float*)d_in[9];

    float *q, *k, *v, *o;
    cudaGetSymbolAddress((void**)&q, g_q);
    cudaGetSymbolAddress((void**)&k, g_k);
    cudaGetSymbolAddress((void**)&v, g_v);
    cudaGetSymbolAddress((void**)&o, g_o);
    __nv_bfloat16 *xh, *xl, *oh, *ol, *wqh, *wql, *wkh, *wkl, *wvh, *wvl, *woh, *wol;
    cudaGetSymbolAddress((void**)&xh, g_xh);   cudaGetSymbolAddress((void**)&xl, g_xl);
    cudaGetSymbolAddress((void**)&oh, g_oh);   cudaGetSymbolAddress((void**)&ol, g_ol);
    cudaGetSymbolAddress((void**)&wqh, g_wqh); cudaGetSymbolAddress((void**)&wql, g_wql);
    cudaGetSymbolAddress((void**)&wkh, g_wkh); cudaGetSymbolAddress((void**)&wkl, g_wkl);
    cudaGetSymbolAddress((void**)&wvh, g_wvh); cudaGetSymbolAddress((void**)&wvl, g_wvl);
    cudaGetSymbolAddress((void**)&woh, g_woh); cudaGetSymbolAddress((void**)&wol, g_wol);

    // splits
    const int nx4 = CM * CE / 4;       // 1M
    const int nw4 = CE * CE / 4;       // 256K
    split_bf16<<<nx4 / 256, 256>>>(query, xh, xl, nx4);
    split_bf16<<<nw4 / 256, 256>>>(Wq, wqh, wql, nw4);
    split_bf16<<<nw4 / 256, 256>>>(Wk, wkh, wkl, nw4);
    split_bf16<<<nw4 / 256, 256>>>(Wv, wvh, wvl, nw4);
    split_bf16<<<nw4 / 256, 256>>>(Wo, woh, wol, nw4);

    dim3 gg(CE / 128, CM / 128);   // (8, 32)
    hgemm_nt_3split<<<gg, 256>>>(xh, xl, wqh, wql, bq, q, CM, CE, CE);
    hgemm_nt_3split<<<gg, 256>>>(xh, xl, wkh, wkl, bk, k, CM, CE, CE);
    hgemm_nt_3split<<<gg, 256>>>(xh, xl, wvh, wvl, bv, v, CM, CE, CE);

    const size_t smem = (3 * 4096 + 64 * 68) * sizeof(float);   // 66560 B
    cudaFuncSetAttribute(yat_attention, cudaFuncAttributeMaxDynamicSharedMemorySize, (int)smem);
    yat_attention<<<dim3(CS / 64, CH, CB), 256, smem>>>(q, k, v, o, alpha);

    split_bf16<<<nx4 / 256, 256>>>(o, oh, ol, nx4);
    hgemm_nt_3split<<<gg, 256>>>(oh, ol, woh, wol, bo, (float*)d_out, CM, CE, CE);
}

// round 6
// speedup vs baseline: 2.5938x; 1.9453x over previous
#include <cuda_runtime.h>
#include <cuda_bf16.h>
#include <math.h>
#include <stdint.h>

#define CB 2
#define CS 2048
#define CE 1024
#define CH 16
#define CD 64
#define CM (CB*CS)          // 4096 tokens
#define YAT_EPS 1e-5f

typedef unsigned long long u64;

__device__ __forceinline__ uint32_t smem_u32(const void* p) {
    uint32_t a;
    asm("{ .reg .u64 t; cvta.to.shared.u64 t, %1; cvt.u32.u64 %0, t; }" : "=r"(a) : "l"(p));
    return a;
}

// ---- mma.sync / ldmatrix helpers (portable to non-'a' sm_103 target) ----
__device__ __forceinline__ void ldsm_x4(uint32_t* r, uint32_t addr) {
    asm volatile("ldmatrix.sync.aligned.m8n8.x4.shared.b16 {%0,%1,%2,%3}, [%4];"
        : "=r"(r[0]), "=r"(r[1]), "=r"(r[2]), "=r"(r[3]) : "r"(addr));
}
__device__ __forceinline__ void ldsm_x4_t(uint32_t* r, uint32_t addr) {
    asm volatile("ldmatrix.sync.aligned.m8n8.x4.trans.shared.b16 {%0,%1,%2,%3}, [%4];"
        : "=r"(r[0]), "=r"(r[1]), "=r"(r[2]), "=r"(r[3]) : "r"(addr));
}
__device__ __forceinline__ void mma_bf16(float* c, const uint32_t* a, const uint32_t* b) {
    asm volatile(
        "mma.sync.aligned.m16n8k16.row.col.f32.bf16.bf16.f32 "
        "{%0,%1,%2,%3}, {%4,%5,%6,%7}, {%8,%9}, {%0,%1,%2,%3};"
        : "+f"(c[0]), "+f"(c[1]), "+f"(c[2]), "+f"(c[3])
        : "r"(a[0]), "r"(a[1]), "r"(a[2]), "r"(a[3]), "r"(b[0]), "r"(b[1]));
}
// pack {lo half = hi16(a), hi half = hi16(b)}  (bf16 truncation split)
__device__ __forceinline__ uint32_t prmt7632(uint32_t a, uint32_t b) {
    uint32_t r; asm("prmt.b32 %0, %1, %2, 0x7632;" : "=r"(r) : "r"(a), "r"(b)); return r;
}
// pack two f32 -> bf16x2 (rn); first arg = low element
__device__ __forceinline__ uint32_t pkbf16x2(float lo, float hi) {
    uint32_t r; asm("cvt.rn.bf16x2.f32 %0, %1, %2;" : "=r"(r) : "f"(hi), "f"(lo)); return r;
}

// ---- Scratch (__device__ globals; allocation-free rule) ----
__device__ float g_q[(size_t)CM*CE];
__device__ float g_k[(size_t)CM*CE];
__device__ float g_v[(size_t)CM*CE];
__device__ float g_o[(size_t)CM*CE];
__device__ __nv_bfloat16 g_xh[(size_t)CM*CE], g_xl[(size_t)CM*CE];   // query split
__device__ __nv_bfloat16 g_oh[(size_t)CM*CE], g_ol[(size_t)CM*CE];   // attn out split
__device__ __nv_bfloat16 g_wqh[(size_t)CE*CE], g_wql[(size_t)CE*CE];
__device__ __nv_bfloat16 g_wkh[(size_t)CE*CE], g_wkl[(size_t)CE*CE];
__device__ __nv_bfloat16 g_wvh[(size_t)CE*CE], g_wvl[(size_t)CE*CE];
__device__ __nv_bfloat16 g_woh[(size_t)CE*CE], g_wol[(size_t)CE*CE];
// q/k/v bf16 splits + head norms for attention
__device__ __nv_bfloat16 g_aqh[(size_t)CM*CE], g_aql[(size_t)CM*CE];
__device__ __nv_bfloat16 g_akh[(size_t)CM*CE], g_akl[(size_t)CM*CE];
__device__ __nv_bfloat16 g_avh[(size_t)CM*CE], g_avl[(size_t)CM*CE];
__device__ float g_qn[(size_t)CH*CM];
__device__ float g_kn[(size_t)CH*CM];

// ---------------------------------------------------------------------------
// fp32 -> (bf16 hi, bf16 lo) split, vectorized
// ---------------------------------------------------------------------------
__global__ __launch_bounds__(256) void split_bf16(
    const float* __restrict__ x, __nv_bfloat16* __restrict__ hi,
    __nv_bfloat16* __restrict__ lo, int n4)
{
    int i = blockIdx.x * blockDim.x + threadIdx.x;
    if (i >= n4) return;
    float4 v = ((const float4*)x)[i];
    union { __nv_bfloat16 b[4]; uint2 u; } H, L;
    float a[4] = {v.x, v.y, v.z, v.w};
#pragma unroll
    for (int j = 0; j < 4; j++) {
        __nv_bfloat16 h = __float2bfloat16(a[j]);
        H.b[j] = h;
        L.b[j] = __float2bfloat16(a[j] - __bfloat162float(h));
    }
    ((uint2*)hi)[i] = H.u;
    ((uint2*)lo)[i] = L.u;
}

// ---------------------------------------------------------------------------
// per-(token, head) squared norms: out[h*CM + tok] = sum_d x[tok*CE + h*64 + d]^2
// ---------------------------------------------------------------------------
__global__ __launch_bounds__(256) void head_norms(
    const float* __restrict__ x, float* __restrict__ out)
{
    int tok = blockIdx.x * 16 + (threadIdx.x >> 4);
    int h = threadIdx.x & 15;
    const float4* p = (const float4*)&x[(size_t)tok * CE + h * CD];
    float s = 0.0f;
#pragma unroll
    for (int i = 0; i < 16; i++) {
        float4 v = p[i];
        s += v.x * v.x + v.y * v.y + v.z * v.z + v.w * v.w;
    }
    out[(size_t)h * CM + tok] = s;
}

// ---------------------------------------------------------------------------
// C[M,N] = A[M,K] @ B[N,K]^T + bias via mma.sync bf16 3-split (unchanged R5).
// ---------------------------------------------------------------------------
#define LDA 40
__global__ __launch_bounds__(256) void hgemm_nt_3split(
    const __nv_bfloat16* __restrict__ Ah, const __nv_bfloat16* __restrict__ Al,
    const __nv_bfloat16* __restrict__ Bh, const __nv_bfloat16* __restrict__ Bl,
    const float* __restrict__ bias, float* __restrict__ C,
    int M, int N, int K)
{
    __shared__ __nv_bfloat16 sAh[128 * LDA], sAl[128 * LDA];
    __shared__ __nv_bfloat16 sBh[128 * LDA], sBl[128 * LDA];

    const int tid = threadIdx.x, lane = tid & 31, wid = tid >> 5;
    const int wm = wid >> 2, wn = wid & 3;
    const int row0 = blockIdx.y * 128, col0 = blockIdx.x * 128;

    const uint32_t uAh = smem_u32(sAh), uAl = smem_u32(sAl);
    const uint32_t uBh = smem_u32(sBh), uBl = smem_u32(sBl);

    float acc[4][4][4];
#pragma unroll
    for (int i = 0; i < 4; i++)
#pragma unroll
        for (int j = 0; j < 4; j++)
#pragma unroll
            for (int f = 0; f < 4; f++) acc[i][j][f] = 0.0f;

    const int a_row = lane & 15, a_kg = lane >> 4;
    const int b_row = ((lane >> 4) & 1) * 8 + (lane & 7);
    const int b_kg  = (lane >> 3) & 1;

    const int gr = tid >> 2;
    const int gc = (tid & 3) * 8;

    for (int k0 = 0; k0 < K; k0 += 32) {
        __syncthreads();
#pragma unroll
        for (int pp = 0; pp < 2; pp++) {
            int r = pp * 64 + gr;
            size_t ga = (size_t)(row0 + r) * K + k0 + gc;
            size_t gb = (size_t)(col0 + r) * K + k0 + gc;
            *(uint4*)&sAh[r * LDA + gc] = *(const uint4*)&Ah[ga];
            *(uint4*)&sAl[r * LDA + gc] = *(const uint4*)&Al[ga];
            *(uint4*)&sBh[r * LDA + gc] = *(const uint4*)&Bh[gb];
            *(uint4*)&sBl[r * LDA + gc] = *(const uint4*)&Bl[gb];
        }
        __syncthreads();

#pragma unroll
        for (int kk = 0; kk < 2; kk++) {
            const uint32_t aoff = ((wm * 64 + a_row) * LDA + kk * 16 + a_kg * 8) * 2;
            const uint32_t boff0 = ((wn * 32 + b_row) * LDA + kk * 16 + b_kg * 8) * 2;
            const uint32_t boff1 = boff0 + 16 * LDA * 2;

            uint32_t bh_f[4][2], bl_f[4][2], af[4][4];
            {
                uint32_t t[4];
                ldsm_x4(t, uBh + boff0);
                bh_f[0][0] = t[0]; bh_f[0][1] = t[1]; bh_f[1][0] = t[2]; bh_f[1][1] = t[3];
                ldsm_x4(t, uBh + boff1);
                bh_f[2][0] = t[0]; bh_f[2][1] = t[1]; bh_f[3][0] = t[2]; bh_f[3][1] = t[3];
                ldsm_x4(t, uBl + boff0);
                bl_f[0][0] = t[0]; bl_f[0][1] = t[1]; bl_f[1][0] = t[2]; bl_f[1][1] = t[3];
                ldsm_x4(t, uBl + boff1);
                bl_f[2][0] = t[0]; bl_f[2][1] = t[1]; bl_f[3][0] = t[2]; bl_f[3][1] = t[3];
            }
#pragma unroll
            for (int mi = 0; mi < 4; mi++)
                ldsm_x4(af[mi], uAh + aoff + mi * 16 * LDA * 2);
#pragma unroll
            for (int mi = 0; mi < 4; mi++)
#pragma unroll
                for (int ni = 0; ni < 4; ni++) {
                    mma_bf16(acc[mi][ni], af[mi], bh_f[ni]);
                    mma_bf16(acc[mi][ni], af[mi], bl_f[ni]);
                }
#pragma unroll
            for (int mi = 0; mi < 4; mi++)
                ldsm_x4(af[mi], uAl + aoff + mi * 16 * LDA * 2);
#pragma unroll
            for (int mi = 0; mi < 4; mi++)
#pragma unroll
                for (int ni = 0; ni < 4; ni++)
                    mma_bf16(acc[mi][ni], af[mi], bh_f[ni]);
        }
    }

    const int erow = lane >> 2, ecol = (lane & 3) * 2;
#pragma unroll
    for (int mi = 0; mi < 4; mi++) {
#pragma unroll
        for (int ni = 0; ni < 4; ni++) {
            int rg = row0 + wm * 64 + mi * 16 + erow;
            int cg = col0 + wn * 32 + ni * 8 + ecol;
            float2 bb = *(const float2*)&bias[cg];
            float2 o0 = {acc[mi][ni][0] + bb.x, acc[mi][ni][1] + bb.y};
            float2 o1 = {acc[mi][ni][2] + bb.x, acc[mi][ni][3] + bb.y};
            *(float2*)&C[(size_t)rg * N + cg] = o0;
            *(float2*)&C[(size_t)(rg + 8) * N + cg] = o1;
        }
    }
}

// ---------------------------------------------------------------------------
// YAT flash attention via mma.sync bf16 3-split.
// CTA: 128 q-rows x 1 head. 8 warps, warp w owns S rows w*16..w*16+15.
// KV tiles of 64. P converted hi/lo in registers (C-frag == A-frag layout).
// ---------------------------------------------------------------------------
#define LDS 72   // bf16 row stride for ldmatrix tiles
// smem element offsets
#define OQH 0
#define OQL 9216
#define OKH 18432
#define OKL 23040
#define OVH 27648
#define OVL 32256
#define ATTN_SMEM (36864*2 + 256)   // 73984 B

__global__ __launch_bounds__(256) void yat_attn_mma(
    const __nv_bfloat16* __restrict__ Qhm, const __nv_bfloat16* __restrict__ Qlm,
    const __nv_bfloat16* __restrict__ Khm, const __nv_bfloat16* __restrict__ Klm,
    const __nv_bfloat16* __restrict__ Vhm, const __nv_bfloat16* __restrict__ Vlm,
    const float* __restrict__ qn, const float* __restrict__ kn,
    float* __restrict__ Om, const float* __restrict__ alphap)
{
    extern __shared__ __nv_bfloat16 sb[];
    __nv_bfloat16* sQh = sb + OQH;
    __nv_bfloat16* sQl = sb + OQL;
    __nv_bfloat16* sKh = sb + OKH;
    __nv_bfloat16* sKl = sb + OKL;
    __nv_bfloat16* sVh = sb + OVH;
    __nv_bfloat16* sVl = sb + OVL;
    float* skn = (float*)(sb + 36864);

    const int tid = threadIdx.x, lane = tid & 31, w = tid >> 5;
    const int g = lane >> 2, tg = lane & 3;
    const int b = blockIdx.z, h = blockIdx.y;
    const int q0 = blockIdx.x * 128;
    const size_t tokq = (size_t)b * CS + q0;

    const float scale = powf(8.0f / logf(65.0f), alphap[0]);

    // load persistent Q hi/lo tile (128 x 64)
    {
        int c8 = tid & 7;
        int rb = tid >> 3;
#pragma unroll
        for (int i = 0; i < 4; i++) {
            int r = rb + i * 32;
            size_t gq = (tokq + r) * CE + h * CD + c8 * 8;
            *(uint4*)&sQh[r * LDS + c8 * 8] = *(const uint4*)&Qhm[gq];
            *(uint4*)&sQl[r * LDS + c8 * 8] = *(const uint4*)&Qlm[gq];
        }
    }

    const float sq0 = qn[(size_t)h * CM + tokq + w * 16 + g];
    const float sq1 = qn[(size_t)h * CM + tokq + w * 16 + g + 8];

    float m0 = -INFINITY, m1 = -INFINITY, l0 = 0.0f, l1 = 0.0f;
    float accO[8][4];
#pragma unroll
    for (int i = 0; i < 8; i++)
#pragma unroll
        for (int j = 0; j < 4; j++) accO[i][j] = 0.0f;

    const uint32_t uQh = smem_u32(sQh), uQl = smem_u32(sQl);
    const uint32_t uKh = smem_u32(sKh), uKl = smem_u32(sKl);
    const uint32_t uVh = smem_u32(sVh), uVl = smem_u32(sVl);

    const int a_row = lane & 15, a_kg = lane >> 4;
    const int b_row = ((lane >> 4) & 1) * 8 + (lane & 7);
    const int b_kg  = (lane >> 3) & 1;

    for (int t = 0; t < CS / 64; t++) {
        __syncthreads();
        {
            int r = tid >> 2, c8 = (tid & 3) * 2;
            size_t gk = ((size_t)b * CS + t * 64 + r) * CE + h * CD;
#pragma unroll
            for (int u = 0; u < 2; u++) {
                int cc = (c8 + u) * 8;
                *(uint4*)&sKh[r * LDS + cc] = *(const uint4*)&Khm[gk + cc];
                *(uint4*)&sKl[r * LDS + cc] = *(const uint4*)&Klm[gk + cc];
                *(uint4*)&sVh[r * LDS + cc] = *(const uint4*)&Vhm[gk + cc];
                *(uint4*)&sVl[r * LDS + cc] = *(const uint4*)&Vlm[gk + cc];
            }
        }
        if (tid < 64) skn[tid] = kn[(size_t)h * CM + b * CS + t * 64 + tid];
        __syncthreads();

        // ---- S = Q K^T (3-split) ----
        float sS[8][4];
#pragma unroll
        for (int i = 0; i < 8; i++)
#pragma unroll
            for (int j = 0; j < 4; j++) sS[i][j] = 0.0f;

#pragma unroll
        for (int kk = 0; kk < 4; kk++) {
            const uint32_t aoff = ((w * 16 + a_row) * LDS + kk * 16 + a_kg * 8) * 2;
            uint32_t ah[4], al[4];
            ldsm_x4(ah, uQh + aoff);
            ldsm_x4(al, uQl + aoff);
#pragma unroll
            for (int nb = 0; nb < 4; nb++) {
                const uint32_t boff = ((nb * 16 + b_row) * LDS + kk * 16 + b_kg * 8) * 2;
                uint32_t th[4], tl[4];
                ldsm_x4(th, uKh + boff);
                ldsm_x4(tl, uKl + boff);
                mma_bf16(sS[2 * nb], ah, th);
                mma_bf16(sS[2 * nb], ah, tl);
                mma_bf16(sS[2 * nb], al, th);
                mma_bf16(sS[2 * nb + 1], ah, th + 2);
                mma_bf16(sS[2 * nb + 1], ah, tl + 2);
                mma_bf16(sS[2 * nb + 1], al, th + 2);
            }
        }

        // ---- YAT score + online softmax ----
        float mx0 = -INFINITY, mx1 = -INFINITY;
#pragma unroll
        for (int ni = 0; ni < 8; ni++) {
            int col = ni * 8 + tg * 2;
            float k0 = skn[col], k1 = skn[col + 1];
            float qk, d, s;
            qk = sS[ni][0]; d = sq0 + k0 - 2.0f * qk + YAT_EPS; s = scale * qk * qk / d;
            sS[ni][0] = s; mx0 = fmaxf(mx0, s);
            qk = sS[ni][1]; d = sq0 + k1 - 2.0f * qk + YAT_EPS; s = scale * qk * qk / d;
            sS[ni][1] = s; mx0 = fmaxf(mx0, s);
            qk = sS[ni][2]; d = sq1 + k0 - 2.0f * qk + YAT_EPS; s = scale * qk * qk / d;
            sS[ni][2] = s; mx1 = fmaxf(mx1, s);
            qk = sS[ni][3]; d = sq1 + k1 - 2.0f * qk + YAT_EPS; s = scale * qk * qk / d;
            sS[ni][3] = s; mx1 = fmaxf(mx1, s);
        }
#pragma unroll
        for (int off = 1; off <= 2; off <<= 1) {
            mx0 = fmaxf(mx0, __shfl_xor_sync(0xffffffffu, mx0, off));
            mx1 = fmaxf(mx1, __shfl_xor_sync(0xffffffffu, mx1, off));
        }
        float nm0 = fmaxf(m0, mx0), nm1 = fmaxf(m1, mx1);
        float corr0 = __expf(m0 - nm0), corr1 = __expf(m1 - nm1);
        m0 = nm0; m1 = nm1;
        float rs0 = 0.0f, rs1 = 0.0f;
#pragma unroll
        for (int ni = 0; ni < 8; ni++) {
            sS[ni][0] = __expf(sS[ni][0] - nm0); rs0 += sS[ni][0];
            sS[ni][1] = __expf(sS[ni][1] - nm0); rs0 += sS[ni][1];
            sS[ni][2] = __expf(sS[ni][2] - nm1); rs1 += sS[ni][2];
            sS[ni][3] = __expf(sS[ni][3] - nm1); rs1 += sS[ni][3];
        }
#pragma unroll
        for (int off = 1; off <= 2; off <<= 1) {
            rs0 += __shfl_xor_sync(0xffffffffu, rs0, off);
            rs1 += __shfl_xor_sync(0xffffffffu, rs1, off);
        }
        l0 = l0 * corr0 + rs0;
        l1 = l1 * corr1 + rs1;
#pragma unroll
        for (int ni = 0; ni < 8; ni++) {
            accO[ni][0] *= corr0; accO[ni][1] *= corr0;
            accO[ni][2] *= corr1; accO[ni][3] *= corr1;
        }

        // ---- O += P @ V (P hi/lo built in registers) ----
#pragma unroll
        for (int kk = 0; kk < 4; kk++) {
            const float* e = sS[2 * kk];
            const float* f = sS[2 * kk + 1];
            uint32_t ph[4], pl[4];
            {
                uint32_t u0, u1;
                float h0, h1;
                u0 = __float_as_uint(e[0]); u1 = __float_as_uint(e[1]);
                ph[0] = prmt7632(u0, u1);
                h0 = __uint_as_float(u0 & 0xffff0000u); h1 = __uint_as_float(u1 & 0xffff0000u);
                pl[0] = pkbf16x2(e[0] - h0, e[1] - h1);
                u0 = __float_as_uint(e[2]); u1 = __float_as_uint(e[3]);
                ph[1] = prmt7632(u0, u1);
                h0 = __uint_as_float(u0 & 0xffff0000u); h1 = __uint_as_float(u1 & 0xffff0000u);
                pl[1] = pkbf16x2(e[2] - h0, e[3] - h1);
                u0 = __float_as_uint(f[0]); u1 = __float_as_uint(f[1]);
                ph[2] = prmt7632(u0, u1);
                h0 = __uint_as_float(u0 & 0xffff0000u); h1 = __uint_as_float(u1 & 0xffff0000u);
                pl[2] = pkbf16x2(f[0] - h0, f[1] - h1);
                u0 = __float_as_uint(f[2]); u1 = __float_as_uint(f[3]);
                ph[3] = prmt7632(u0, u1);
                h0 = __uint_as_float(u0 & 0xffff0000u); h1 = __uint_as_float(u1 & 0xffff0000u);
                pl[3] = pkbf16x2(f[2] - h0, f[3] - h1);
            }
#pragma unroll
            for (int db = 0; db < 4; db++) {
                const uint32_t voff = ((kk * 16 + (lane & 15)) * LDS + db * 16 + (lane >> 4) * 8) * 2;
                uint32_t th[4], tl[4];
                ldsm_x4_t(th, uVh + voff);
                ldsm_x4_t(tl, uVl + voff);
                mma_bf16(accO[2 * db], ph, th);
                mma_bf16(accO[2 * db], ph, tl);
                mma_bf16(accO[2 * db], pl, th);
                mma_bf16(accO[2 * db + 1], ph, th + 2);
                mma_bf16(accO[2 * db + 1], ph, tl + 2);
                mma_bf16(accO[2 * db + 1], pl, th + 2);
            }
        }
    }

    // epilogue
    float inv0 = 1.0f / l0, inv1 = 1.0f / l1;
    size_t ro = (tokq + w * 16 + g) * CE + h * CD;
#pragma unroll
    for (int ni = 0; ni < 8; ni++) {
        int c = ni * 8 + tg * 2;
        float2 o0 = {accO[ni][0] * inv0, accO[ni][1] * inv0};
        float2 o1 = {accO[ni][2] * inv1, accO[ni][3] * inv1};
        *(float2*)&Om[ro + c] = o0;
        *(float2*)&Om[ro + 8 * CE + c] = o1;
    }
}

// ---------------------------------------------------------------------------
extern "C" void kernel_launch(void* const* d_in, const int* in_sizes, int n_in,
                              void* d_out, int out_size)
{
    (void)in_sizes; (void)n_in; (void)out_size;
    const float* query = (const float*)d_in[0];
    const float* Wq    = (const float*)d_in[1];
    const float* bq    = (const float*)d_in[2];
    const float* Wk    = (const float*)d_in[3];
    const float* bk    = (const float*)d_in[4];
    const float* Wv    = (const float*)d_in[5];
    const float* bv    = (const float*)d_in[6];
    const float* Wo    = (const float*)d_in[7];
    const float* bo    = (const float*)d_in[8];
    const float* alpha = (const float*)d_in[9];

    float *q, *k, *v, *o, *qn, *kn;
    cudaGetSymbolAddress((void**)&q, g_q);
    cudaGetSymbolAddress((void**)&k, g_k);
    cudaGetSymbolAddress((void**)&v, g_v);
    cudaGetSymbolAddress((void**)&o, g_o);
    cudaGetSymbolAddress((void**)&qn, g_qn);
    cudaGetSymbolAddress((void**)&kn, g_kn);
    __nv_bfloat16 *xh, *xl, *oh, *ol, *wqh, *wql, *wkh, *wkl, *wvh, *wvl, *woh, *wol;
    __nv_bfloat16 *aqh, *aql, *akh, *akl, *avh, *avl;
    cudaGetSymbolAddress((void**)&xh, g_xh);   cudaGetSymbolAddress((void**)&xl, g_xl);
    cudaGetSymbolAddress((void**)&oh, g_oh);   cudaGetSymbolAddress((void**)&ol, g_ol);
    cudaGetSymbolAddress((void**)&wqh, g_wqh); cudaGetSymbolAddress((void**)&wql, g_wql);
    cudaGetSymbolAddress((void**)&wkh, g_wkh); cudaGetSymbolAddress((void**)&wkl, g_wkl);
    cudaGetSymbolAddress((void**)&wvh, g_wvh); cudaGetSymbolAddress((void**)&wvl, g_wvl);
    cudaGetSymbolAddress((void**)&woh, g_woh); cudaGetSymbolAddress((void**)&wol, g_wol);
    cudaGetSymbolAddress((void**)&aqh, g_aqh); cudaGetSymbolAddress((void**)&aql, g_aql);
    cudaGetSymbolAddress((void**)&akh, g_akh); cudaGetSymbolAddress((void**)&akl, g_akl);
    cudaGetSymbolAddress((void**)&avh, g_avh); cudaGetSymbolAddress((void**)&avl, g_avl);

    const int nx4 = CM * CE / 4;
    const int nw4 = CE * CE / 4;
    split_bf16<<<nx4 / 256, 256>>>(query, xh, xl, nx4);
    split_bf16<<<nw4 / 256, 256>>>(Wq, wqh, wql, nw4);
    split_bf16<<<nw4 / 256, 256>>>(Wk, wkh, wkl, nw4);
    split_bf16<<<nw4 / 256, 256>>>(Wv, wvh, wvl, nw4);
    split_bf16<<<nw4 / 256, 256>>>(Wo, woh, wol, nw4);

    dim3 gg(CE / 128, CM / 128);
    hgemm_nt_3split<<<gg, 256>>>(xh, xl, wqh, wql, bq, q, CM, CE, CE);
    hgemm_nt_3split<<<gg, 256>>>(xh, xl, wkh, wkl, bk, k, CM, CE, CE);
    hgemm_nt_3split<<<gg, 256>>>(xh, xl, wvh, wvl, bv, v, CM, CE, CE);

    // attention prep: bf16 splits of q/k/v + head norms
    split_bf16<<<nx4 / 256, 256>>>(q, aqh, aql, nx4);
    split_bf16<<<nx4 / 256, 256>>>(k, akh, akl, nx4);
    split_bf16<<<nx4 / 256, 256>>>(v, avh, avl, nx4);
    head_norms<<<CM / 16, 256>>>(q, qn);
    head_norms<<<CM / 16, 256>>>(k, kn);

    cudaFuncSetAttribute(yat_attn_mma, cudaFuncAttributeMaxDynamicSharedMemorySize, ATTN_SMEM);
    yat_attn_mma<<<dim3(CS / 128, CH, CB), 256, ATTN_SMEM>>>(
        aqh, aql, akh, akl, avh, avl, qn, kn, o, alpha);

    split_bf16<<<nx4 / 256, 256>>>(o, oh, ol, nx4);
    hgemm_nt_3split<<<gg, 256>>>(oh, ol, woh, wol, bo, (float*)d_out, CM, CE, CE);
}

// round 7
// speedup vs baseline: 2.6934x; 1.0384x over previous
#include <cuda_runtime.h>
#include <cuda_bf16.h>
#include <math.h>
#include <stdint.h>

#define CB 2
#define CS 2048
#define CE 1024
#define CH 16
#define CD 64
#define CM (CB*CS)          // 4096 tokens
#define YAT_EPS 1e-5f

__device__ __forceinline__ uint32_t smem_u32(const void* p) {
    uint32_t a;
    asm("{ .reg .u64 t; cvta.to.shared.u64 t, %1; cvt.u32.u64 %0, t; }" : "=r"(a) : "l"(p));
    return a;
}

// ---- mma.sync / ldmatrix / cp.async helpers (portable to non-'a' sm_103) ----
__device__ __forceinline__ void ldsm_x4(uint32_t* r, uint32_t addr) {
    asm volatile("ldmatrix.sync.aligned.m8n8.x4.shared.b16 {%0,%1,%2,%3}, [%4];"
        : "=r"(r[0]), "=r"(r[1]), "=r"(r[2]), "=r"(r[3]) : "r"(addr));
}
__device__ __forceinline__ void ldsm_x4_t(uint32_t* r, uint32_t addr) {
    asm volatile("ldmatrix.sync.aligned.m8n8.x4.trans.shared.b16 {%0,%1,%2,%3}, [%4];"
        : "=r"(r[0]), "=r"(r[1]), "=r"(r[2]), "=r"(r[3]) : "r"(addr));
}
__device__ __forceinline__ void mma_bf16(float* c, const uint32_t* a, const uint32_t* b) {
    asm volatile(
        "mma.sync.aligned.m16n8k16.row.col.f32.bf16.bf16.f32 "
        "{%0,%1,%2,%3}, {%4,%5,%6,%7}, {%8,%9}, {%0,%1,%2,%3};"
        : "+f"(c[0]), "+f"(c[1]), "+f"(c[2]), "+f"(c[3])
        : "r"(a[0]), "r"(a[1]), "r"(a[2]), "r"(a[3]), "r"(b[0]), "r"(b[1]));
}
__device__ __forceinline__ uint32_t prmt7632(uint32_t a, uint32_t b) {
    uint32_t r; asm("prmt.b32 %0, %1, %2, 0x7632;" : "=r"(r) : "r"(a), "r"(b)); return r;
}
__device__ __forceinline__ uint32_t pkbf16x2(float lo, float hi) {
    uint32_t r; asm("cvt.rn.bf16x2.f32 %0, %1, %2;" : "=r"(r) : "f"(hi), "f"(lo)); return r;
}
__device__ __forceinline__ void cpasync16(uint32_t dst, const void* src) {
    asm volatile("cp.async.cg.shared.global [%0], [%1], 16;" :: "r"(dst), "l"(src));
}
#define CP_COMMIT() asm volatile("cp.async.commit_group;" ::: "memory")
#define CP_WAIT(n)  asm volatile("cp.async.wait_group %0;" :: "n"(n) : "memory")

// ---- Scratch (__device__ globals; allocation-free rule) ----
__device__ __nv_bfloat16 g_xh[(size_t)CM*CE], g_xl[(size_t)CM*CE];   // query split
__device__ __nv_bfloat16 g_oh[(size_t)CM*CE], g_ol[(size_t)CM*CE];   // attn out split
__device__ __nv_bfloat16 g_wqh[(size_t)CE*CE], g_wql[(size_t)CE*CE];
__device__ __nv_bfloat16 g_wkh[(size_t)CE*CE], g_wkl[(size_t)CE*CE];
__device__ __nv_bfloat16 g_wvh[(size_t)CE*CE], g_wvl[(size_t)CE*CE];
__device__ __nv_bfloat16 g_woh[(size_t)CE*CE], g_wol[(size_t)CE*CE];
__device__ __nv_bfloat16 g_aqh[(size_t)CM*CE], g_aql[(size_t)CM*CE];
__device__ __nv_bfloat16 g_akh[(size_t)CM*CE], g_akl[(size_t)CM*CE];
__device__ __nv_bfloat16 g_avh[(size_t)CM*CE], g_avl[(size_t)CM*CE];
__device__ float g_qn[(size_t)CH*CM];
__device__ float g_kn[(size_t)CH*CM];

// ---------------------------------------------------------------------------
// fp32 -> (bf16 hi, bf16 lo) split, vectorized
// ---------------------------------------------------------------------------
__global__ __launch_bounds__(256) void split_bf16(
    const float* __restrict__ x, __nv_bfloat16* __restrict__ hi,
    __nv_bfloat16* __restrict__ lo, int n4)
{
    int i = blockIdx.x * blockDim.x + threadIdx.x;
    if (i >= n4) return;
    float4 v = ((const float4*)x)[i];
    union { __nv_bfloat16 b[4]; uint2 u; } H, L;
    float a[4] = {v.x, v.y, v.z, v.w};
#pragma unroll
    for (int j = 0; j < 4; j++) {
        __nv_bfloat16 h = __float2bfloat16(a[j]);
        H.b[j] = h;
        L.b[j] = __float2bfloat16(a[j] - __bfloat162float(h));
    }
    ((uint2*)hi)[i] = H.u;
    ((uint2*)lo)[i] = L.u;
}

// ---------------------------------------------------------------------------
// per-(token, head) squared norms from hi/lo pairs
// ---------------------------------------------------------------------------
__global__ __launch_bounds__(256) void head_norms_hl(
    const __nv_bfloat16* __restrict__ hi, const __nv_bfloat16* __restrict__ lo,
    float* __restrict__ out)
{
    int tok = blockIdx.x * 16 + (threadIdx.x >> 4);
    int h = threadIdx.x & 15;
    size_t base = (size_t)tok * CE + h * CD;
    float s = 0.0f;
#pragma unroll
    for (int i = 0; i < 8; i++) {
        union { uint4 u; __nv_bfloat16 b[8]; } H, L;
        H.u = *(const uint4*)&hi[base + i * 8];
        L.u = *(const uint4*)&lo[base + i * 8];
#pragma unroll
        for (int j = 0; j < 8; j++) {
            float f = __bfloat162float(H.b[j]) + __bfloat162float(L.b[j]);
            s += f * f;
        }
    }
    out[(size_t)h * CM + tok] = s;
}

// ---------------------------------------------------------------------------
// C = A @ B^T + bias via mma.sync bf16 3-split, cp.async 2-stage pipeline.
// 128x128 CTA tile, BK=32, 256 threads (8 warps, 2x4), 64x32 per warp.
// Optional outputs: C (fp32), Chi/Clo (bf16 split).
// ---------------------------------------------------------------------------
#define LDA 40
#define STB (128*LDA*2)          // bytes per array per stage = 10240
#define HG_SMEM (2*4*STB)        // 81920 B

__global__ __launch_bounds__(256) void hgemm_nt_3split(
    const __nv_bfloat16* __restrict__ Ah, const __nv_bfloat16* __restrict__ Al,
    const __nv_bfloat16* __restrict__ Bh, const __nv_bfloat16* __restrict__ Bl,
    const float* __restrict__ bias, float* __restrict__ C,
    __nv_bfloat16* __restrict__ Chi, __nv_bfloat16* __restrict__ Clo,
    int M, int N, int K)
{
    extern __shared__ __nv_bfloat16 smem[];
    const uint32_t uS = smem_u32(smem);

    const int tid = threadIdx.x, lane = tid & 31, wid = tid >> 5;
    const int wm = wid >> 2, wn = wid & 3;
    const int row0 = blockIdx.y * 128, col0 = blockIdx.x * 128;

    float acc[4][4][4];
#pragma unroll
    for (int i = 0; i < 4; i++)
#pragma unroll
        for (int j = 0; j < 4; j++)
#pragma unroll
            for (int f = 0; f < 4; f++) acc[i][j][f] = 0.0f;

    const int a_row = lane & 15, a_kg = lane >> 4;
    const int b_row = ((lane >> 4) & 1) * 8 + (lane & 7);
    const int b_kg  = (lane >> 3) & 1;

    const int gr = tid >> 2;
    const int gc = (tid & 3) * 8;

    const int NT = K / 32;

    // stage loader: arrays 0=Ah 1=Al 2=Bh 3=Bl
    auto load_st = [&](int s, int t) {
        const int k0 = t * 32;
        const uint32_t sbase = uS + s * 4 * STB;
#pragma unroll
        for (int pp = 0; pp < 2; pp++) {
            int r = pp * 64 + gr;
            uint32_t doff = (uint32_t)(r * LDA + gc) * 2;
            size_t ga = (size_t)(row0 + r) * K + k0 + gc;
            size_t gb = (size_t)(col0 + r) * K + k0 + gc;
            cpasync16(sbase + 0 * STB + doff, &Ah[ga]);
            cpasync16(sbase + 1 * STB + doff, &Al[ga]);
            cpasync16(sbase + 2 * STB + doff, &Bh[gb]);
            cpasync16(sbase + 3 * STB + doff, &Bl[gb]);
        }
    };

    load_st(0, 0);
    CP_COMMIT();

    for (int t = 0; t < NT; t++) {
        if (t + 1 < NT) {
            load_st((t + 1) & 1, t + 1);
            CP_COMMIT();
            CP_WAIT(1);
        } else {
            CP_WAIT(0);
        }
        __syncthreads();

        const uint32_t sA_h = uS + ((t & 1) * 4 + 0) * STB;
        const uint32_t sA_l = uS + ((t & 1) * 4 + 1) * STB;
        const uint32_t sB_h = uS + ((t & 1) * 4 + 2) * STB;
        const uint32_t sB_l = uS + ((t & 1) * 4 + 3) * STB;

#pragma unroll
        for (int kk = 0; kk < 2; kk++) {
            const uint32_t aoff = ((wm * 64 + a_row) * LDA + kk * 16 + a_kg * 8) * 2;
            const uint32_t boff0 = ((wn * 32 + b_row) * LDA + kk * 16 + b_kg * 8) * 2;
            const uint32_t boff1 = boff0 + 16 * LDA * 2;

            uint32_t bh_f[4][2], bl_f[4][2], af[4][4];
            {
                uint32_t tt[4];
                ldsm_x4(tt, sB_h + boff0);
                bh_f[0][0] = tt[0]; bh_f[0][1] = tt[1]; bh_f[1][0] = tt[2]; bh_f[1][1] = tt[3];
                ldsm_x4(tt, sB_h + boff1);
                bh_f[2][0] = tt[0]; bh_f[2][1] = tt[1]; bh_f[3][0] = tt[2]; bh_f[3][1] = tt[3];
                ldsm_x4(tt, sB_l + boff0);
                bl_f[0][0] = tt[0]; bl_f[0][1] = tt[1]; bl_f[1][0] = tt[2]; bl_f[1][1] = tt[3];
                ldsm_x4(tt, sB_l + boff1);
                bl_f[2][0] = tt[0]; bl_f[2][1] = tt[1]; bl_f[3][0] = tt[2]; bl_f[3][1] = tt[3];
            }
#pragma unroll
            for (int mi = 0; mi < 4; mi++)
                ldsm_x4(af[mi], sA_h + aoff + mi * 16 * LDA * 2);
#pragma unroll
            for (int mi = 0; mi < 4; mi++)
#pragma unroll
                for (int ni = 0; ni < 4; ni++) {
                    mma_bf16(acc[mi][ni], af[mi], bh_f[ni]);
                    mma_bf16(acc[mi][ni], af[mi], bl_f[ni]);
                }
#pragma unroll
            for (int mi = 0; mi < 4; mi++)
                ldsm_x4(af[mi], sA_l + aoff + mi * 16 * LDA * 2);
#pragma unroll
            for (int mi = 0; mi < 4; mi++)
#pragma unroll
                for (int ni = 0; ni < 4; ni++)
                    mma_bf16(acc[mi][ni], af[mi], bh_f[ni]);
        }
        __syncthreads();
    }

    const int erow = lane >> 2, ecol = (lane & 3) * 2;
#pragma unroll
    for (int mi = 0; mi < 4; mi++) {
#pragma unroll
        for (int ni = 0; ni < 4; ni++) {
            int rg = row0 + wm * 64 + mi * 16 + erow;
            int cg = col0 + wn * 32 + ni * 8 + ecol;
            float2 bb = *(const float2*)&bias[cg];
            float o00 = acc[mi][ni][0] + bb.x, o01 = acc[mi][ni][1] + bb.y;
            float o10 = acc[mi][ni][2] + bb.x, o11 = acc[mi][ni][3] + bb.y;
            size_t i0 = (size_t)rg * N + cg, i1 = (size_t)(rg + 8) * N + cg;
            if (C) {
                *(float2*)&C[i0] = make_float2(o00, o01);
                *(float2*)&C[i1] = make_float2(o10, o11);
            }
            if (Chi) {
                __nv_bfloat16 h00 = __float2bfloat16(o00), h01 = __float2bfloat16(o01);
                __nv_bfloat16 h10 = __float2bfloat16(o10), h11 = __float2bfloat16(o11);
                *(__nv_bfloat162*)&Chi[i0] = __nv_bfloat162(h00, h01);
                *(__nv_bfloat162*)&Chi[i1] = __nv_bfloat162(h10, h11);
                *(__nv_bfloat162*)&Clo[i0] = __nv_bfloat162(
                    __float2bfloat16(o00 - __bfloat162float(h00)),
                    __float2bfloat16(o01 - __bfloat162float(h01)));
                *(__nv_bfloat162*)&Clo[i1] = __nv_bfloat162(
                    __float2bfloat16(o10 - __bfloat162float(h10)),
                    __float2bfloat16(o11 - __bfloat162float(h11)));
            }
        }
    }
}

// ---------------------------------------------------------------------------
// YAT flash attention via mma.sync bf16 3-split (R6 structure).
// Epilogue now writes hi/lo bf16 splits directly.
// ---------------------------------------------------------------------------
#define LDS 72
#define OQH 0
#define OQL 9216
#define OKH 18432
#define OKL 23040
#define OVH 27648
#define OVL 32256
#define ATTN_SMEM (36864*2 + 256)

__global__ __launch_bounds__(256) void yat_attn_mma(
    const __nv_bfloat16* __restrict__ Qhm, const __nv_bfloat16* __restrict__ Qlm,
    const __nv_bfloat16* __restrict__ Khm, const __nv_bfloat16* __restrict__ Klm,
    const __nv_bfloat16* __restrict__ Vhm, const __nv_bfloat16* __restrict__ Vlm,
    const float* __restrict__ qn, const float* __restrict__ kn,
    __nv_bfloat16* __restrict__ Ohm, __nv_bfloat16* __restrict__ Olm,
    const float* __restrict__ alphap)
{
    extern __shared__ __nv_bfloat16 sb[];
    __nv_bfloat16* sQh = sb + OQH;
    __nv_bfloat16* sQl = sb + OQL;
    __nv_bfloat16* sKh = sb + OKH;
    __nv_bfloat16* sKl = sb + OKL;
    __nv_bfloat16* sVh = sb + OVH;
    __nv_bfloat16* sVl = sb + OVL;
    float* skn = (float*)(sb + 36864);

    const int tid = threadIdx.x, lane = tid & 31, w = tid >> 5;
    const int g = lane >> 2, tg = lane & 3;
    const int b = blockIdx.z, h = blockIdx.y;
    const int q0 = blockIdx.x * 128;
    const size_t tokq = (size_t)b * CS + q0;

    const float scale = powf(8.0f / logf(65.0f), alphap[0]);

    {
        int c8 = tid & 7;
        int rb = tid >> 3;
#pragma unroll
        for (int i = 0; i < 4; i++) {
            int r = rb + i * 32;
            size_t gq = (tokq + r) * CE + h * CD + c8 * 8;
            *(uint4*)&sQh[r * LDS + c8 * 8] = *(const uint4*)&Qhm[gq];
            *(uint4*)&sQl[r * LDS + c8 * 8] = *(const uint4*)&Qlm[gq];
        }
    }

    const float sq0 = qn[(size_t)h * CM + tokq + w * 16 + g];
    const float sq1 = qn[(size_t)h * CM + tokq + w * 16 + g + 8];

    float m0 = -INFINITY, m1 = -INFINITY, l0 = 0.0f, l1 = 0.0f;
    float accO[8][4];
#pragma unroll
    for (int i = 0; i < 8; i++)
#pragma unroll
        for (int j = 0; j < 4; j++) accO[i][j] = 0.0f;

    const uint32_t uQh = smem_u32(sQh), uQl = smem_u32(sQl);
    const uint32_t uKh = smem_u32(sKh), uKl = smem_u32(sKl);
    const uint32_t uVh = smem_u32(sVh), uVl = smem_u32(sVl);

    const int a_row = lane & 15, a_kg = lane >> 4;
    const int b_row = ((lane >> 4) & 1) * 8 + (lane & 7);
    const int b_kg  = (lane >> 3) & 1;

    for (int t = 0; t < CS / 64; t++) {
        __syncthreads();
        {
            int r = tid >> 2, c8 = (tid & 3) * 2;
            size_t gk = ((size_t)b * CS + t * 64 + r) * CE + h * CD;
#pragma unroll
            for (int u = 0; u < 2; u++) {
                int cc = (c8 + u) * 8;
                *(uint4*)&sKh[r * LDS + cc] = *(const uint4*)&Khm[gk + cc];
                *(uint4*)&sKl[r * LDS + cc] = *(const uint4*)&Klm[gk + cc];
                *(uint4*)&sVh[r * LDS + cc] = *(const uint4*)&Vhm[gk + cc];
                *(uint4*)&sVl[r * LDS + cc] = *(const uint4*)&Vlm[gk + cc];
            }
        }
        if (tid < 64) skn[tid] = kn[(size_t)h * CM + b * CS + t * 64 + tid];
        __syncthreads();

        float sS[8][4];
#pragma unroll
        for (int i = 0; i < 8; i++)
#pragma unroll
            for (int j = 0; j < 4; j++) sS[i][j] = 0.0f;

#pragma unroll
        for (int kk = 0; kk < 4; kk++) {
            const uint32_t aoff = ((w * 16 + a_row) * LDS + kk * 16 + a_kg * 8) * 2;
            uint32_t ah[4], al[4];
            ldsm_x4(ah, uQh + aoff);
            ldsm_x4(al, uQl + aoff);
#pragma unroll
            for (int nb = 0; nb < 4; nb++) {
                const uint32_t boff = ((nb * 16 + b_row) * LDS + kk * 16 + b_kg * 8) * 2;
                uint32_t th[4], tl[4];
                ldsm_x4(th, uKh + boff);
                ldsm_x4(tl, uKl + boff);
                mma_bf16(sS[2 * nb], ah, th);
                mma_bf16(sS[2 * nb], ah, tl);
                mma_bf16(sS[2 * nb], al, th);
                mma_bf16(sS[2 * nb + 1], ah, th + 2);
                mma_bf16(sS[2 * nb + 1], ah, tl + 2);
                mma_bf16(sS[2 * nb + 1], al, th + 2);
            }
        }

        float mx0 = -INFINITY, mx1 = -INFINITY;
#pragma unroll
        for (int ni = 0; ni < 8; ni++) {
            int col = ni * 8 + tg * 2;
            float k0 = skn[col], k1 = skn[col + 1];
            float qk, d, s;
            qk = sS[ni][0]; d = sq0 + k0 - 2.0f * qk + YAT_EPS; s = scale * qk * qk / d;
            sS[ni][0] = s; mx0 = fmaxf(mx0, s);
            qk = sS[ni][1]; d = sq0 + k1 - 2.0f * qk + YAT_EPS; s = scale * qk * qk / d;
            sS[ni][1] = s; mx0 = fmaxf(mx0, s);
            qk = sS[ni][2]; d = sq1 + k0 - 2.0f * qk + YAT_EPS; s = scale * qk * qk / d;
            sS[ni][2] = s; mx1 = fmaxf(mx1, s);
            qk = sS[ni][3]; d = sq1 + k1 - 2.0f * qk + YAT_EPS; s = scale * qk * qk / d;
            sS[ni][3] = s; mx1 = fmaxf(mx1, s);
        }
#pragma unroll
        for (int off = 1; off <= 2; off <<= 1) {
            mx0 = fmaxf(mx0, __shfl_xor_sync(0xffffffffu, mx0, off));
            mx1 = fmaxf(mx1, __shfl_xor_sync(0xffffffffu, mx1, off));
        }
        float nm0 = fmaxf(m0, mx0), nm1 = fmaxf(m1, mx1);
        float corr0 = __expf(m0 - nm0), corr1 = __expf(m1 - nm1);
        m0 = nm0; m1 = nm1;
        float rs0 = 0.0f, rs1 = 0.0f;
#pragma unroll
        for (int ni = 0; ni < 8; ni++) {
            sS[ni][0] = __expf(sS[ni][0] - nm0); rs0 += sS[ni][0];
            sS[ni][1] = __expf(sS[ni][1] - nm0); rs0 += sS[ni][1];
            sS[ni][2] = __expf(sS[ni][2] - nm1); rs1 += sS[ni][2];
            sS[ni][3] = __expf(sS[ni][3] - nm1); rs1 += sS[ni][3];
        }
#pragma unroll
        for (int off = 1; off <= 2; off <<= 1) {
            rs0 += __shfl_xor_sync(0xffffffffu, rs0, off);
            rs1 += __shfl_xor_sync(0xffffffffu, rs1, off);
        }
        l0 = l0 * corr0 + rs0;
        l1 = l1 * corr1 + rs1;
#pragma unroll
        for (int ni = 0; ni < 8; ni++) {
            accO[ni][0] *= corr0; accO[ni][1] *= corr0;
            accO[ni][2] *= corr1; accO[ni][3] *= corr1;
        }

#pragma unroll
        for (int kk = 0; kk < 4; kk++) {
            const float* e = sS[2 * kk];
            const float* f = sS[2 * kk + 1];
            uint32_t ph[4], pl[4];
            {
                uint32_t u0, u1;
                float h0, h1;
                u0 = __float_as_uint(e[0]); u1 = __float_as_uint(e[1]);
                ph[0] = prmt7632(u0, u1);
                h0 = __uint_as_float(u0 & 0xffff0000u); h1 = __uint_as_float(u1 & 0xffff0000u);
                pl[0] = pkbf16x2(e[0] - h0, e[1] - h1);
                u0 = __float_as_uint(e[2]); u1 = __float_as_uint(e[3]);
                ph[1] = prmt7632(u0, u1);
                h0 = __uint_as_float(u0 & 0xffff0000u); h1 = __uint_as_float(u1 & 0xffff0000u);
                pl[1] = pkbf16x2(e[2] - h0, e[3] - h1);
                u0 = __float_as_uint(f[0]); u1 = __float_as_uint(f[1]);
                ph[2] = prmt7632(u0, u1);
                h0 = __uint_as_float(u0 & 0xffff0000u); h1 = __uint_as_float(u1 & 0xffff0000u);
                pl[2] = pkbf16x2(f[0] - h0, f[1] - h1);
                u0 = __float_as_uint(f[2]); u1 = __float_as_uint(f[3]);
                ph[3] = prmt7632(u0, u1);
                h0 = __uint_as_float(u0 & 0xffff0000u); h1 = __uint_as_float(u1 & 0xffff0000u);
                pl[3] = pkbf16x2(f[2] - h0, f[3] - h1);
            }
#pragma unroll
            for (int db = 0; db < 4; db++) {
                const uint32_t voff = ((kk * 16 + (lane & 15)) * LDS + db * 16 + (lane >> 4) * 8) * 2;
                uint32_t th[4], tl[4];
                ldsm_x4_t(th, uVh + voff);
                ldsm_x4_t(tl, uVl + voff);
                mma_bf16(accO[2 * db], ph, th);
                mma_bf16(accO[2 * db], ph, tl);
                mma_bf16(accO[2 * db], pl, th);
                mma_bf16(accO[2 * db + 1], ph, th + 2);
                mma_bf16(accO[2 * db + 1], ph, tl + 2);
                mma_bf16(accO[2 * db + 1], pl, th + 2);
            }
        }
    }

    // epilogue: normalize, split to hi/lo bf16, store
    float inv0 = 1.0f / l0, inv1 = 1.0f / l1;
    size_t ro = (tokq + w * 16 + g) * CE + h * CD;
#pragma unroll
    for (int ni = 0; ni < 8; ni++) {
        int c = ni * 8 + tg * 2;
        float o00 = accO[ni][0] * inv0, o01 = accO[ni][1] * inv0;
        float o10 = accO[ni][2] * inv1, o11 = accO[ni][3] * inv1;
        __nv_bfloat16 h00 = __float2bfloat16(o00), h01 = __float2bfloat16(o01);
        __nv_bfloat16 h10 = __float2bfloat16(o10), h11 = __float2bfloat16(o11);
        *(__nv_bfloat162*)&Ohm[ro + c] = __nv_bfloat162(h00, h01);
        *(__nv_bfloat162*)&Ohm[ro + 8 * CE + c] = __nv_bfloat162(h10, h11);
        *(__nv_bfloat162*)&Olm[ro + c] = __nv_bfloat162(
            __float2bfloat16(o00 - __bfloat162float(h00)),
            __float2bfloat16(o01 - __bfloat162float(h01)));
        *(__nv_bfloat162*)&Olm[ro + 8 * CE + c] = __nv_bfloat162(
            __float2bfloat16(o10 - __bfloat162float(h10)),
            __float2bfloat16(o11 - __bfloat162float(h11)));
    }
}

// ---------------------------------------------------------------------------
extern "C" void kernel_launch(void* const* d_in, const int* in_sizes, int n_in,
                              void* d_out, int out_size)
{
    (void)in_sizes; (void)n_in; (void)out_size;
    const float* query = (const float*)d_in[0];
    const float* Wq    = (const float*)d_in[1];
    const float* bq    = (const float*)d_in[2];
    const float* Wk    = (const float*)d_in[3];
    const float* bk    = (const float*)d_in[4];
    const float* Wv    = (const float*)d_in[5];
    const float* bv    = (const float*)d_in[6];
    const float* Wo    = (const float*)d_in[7];
    const float* bo    = (const float*)d_in[8];
    const float* alpha = (const float*)d_in[9];

    float *qn, *kn;
    cudaGetSymbolAddress((void**)&qn, g_qn);
    cudaGetSymbolAddress((void**)&kn, g_kn);
    __nv_bfloat16 *xh, *xl, *oh, *ol, *wqh, *wql, *wkh, *wkl, *wvh, *wvl, *woh, *wol;
    __nv_bfloat16 *aqh, *aql, *akh, *akl, *avh, *avl;
    cudaGetSymbolAddress((void**)&xh, g_xh);   cudaGetSymbolAddress((void**)&xl, g_xl);
    cudaGetSymbolAddress((void**)&oh, g_oh);   cudaGetSymbolAddress((void**)&ol, g_ol);
    cudaGetSymbolAddress((void**)&wqh, g_wqh); cudaGetSymbolAddress((void**)&wql, g_wql);
    cudaGetSymbolAddress((void**)&wkh, g_wkh); cudaGetSymbolAddress((void**)&wkl, g_wkl);
    cudaGetSymbolAddress((void**)&wvh, g_wvh); cudaGetSymbolAddress((void**)&wvl, g_wvl);
    cudaGetSymbolAddress((void**)&woh, g_woh); cudaGetSymbolAddress((void**)&wol, g_wol);
    cudaGetSymbolAddress((void**)&aqh, g_aqh); cudaGetSymbolAddress((void**)&aql, g_aql);
    cudaGetSymbolAddress((void**)&akh, g_akh); cudaGetSymbolAddress((void**)&akl, g_akl);
    cudaGetSymbolAddress((void**)&avh, g_avh); cudaGetSymbolAddress((void**)&avl, g_avl);

    const int nx4 = CM * CE / 4;
    const int nw4 = CE * CE / 4;
    split_bf16<<<nx4 / 256, 256>>>(query, xh, xl, nx4);
    split_bf16<<<nw4 / 256, 256>>>(Wq, wqh, wql, nw4);
    split_bf16<<<nw4 / 256, 256>>>(Wk, wkh, wkl, nw4);
    split_bf16<<<nw4 / 256, 256>>>(Wv, wvh, wvl, nw4);
    split_bf16<<<nw4 / 256, 256>>>(Wo, woh, wol, nw4);

    cudaFuncSetAttribute(hgemm_nt_3split, cudaFuncAttributeMaxDynamicSharedMemorySize, HG_SMEM);
    dim3 gg(CE / 128, CM / 128);
    // QKV projections: write bf16 splits directly (no fp32 output)
    hgemm_nt_3split<<<gg, 256, HG_SMEM>>>(xh, xl, wqh, wql, bq, nullptr, aqh, aql, CM, CE, CE);
    hgemm_nt_3split<<<gg, 256, HG_SMEM>>>(xh, xl, wkh, wkl, bk, nullptr, akh, akl, CM, CE, CE);
    hgemm_nt_3split<<<gg, 256, HG_SMEM>>>(xh, xl, wvh, wvl, bv, nullptr, avh, avl, CM, CE, CE);

    head_norms_hl<<<CM / 16, 256>>>(aqh, aql, qn);
    head_norms_hl<<<CM / 16, 256>>>(akh, akl, kn);

    cudaFuncSetAttribute(yat_attn_mma, cudaFuncAttributeMaxDynamicSharedMemorySize, ATTN_SMEM);
    yat_attn_mma<<<dim3(CS / 128, CH, CB), 256, ATTN_SMEM>>>(
        aqh, aql, akh, akl, avh, avl, qn, kn, oh, ol, alpha);

    // output projection: fp32 result straight to d_out
    hgemm_nt_3split<<<gg, 256, HG_SMEM>>>(oh, ol, woh, wol, bo, (float*)d_out, nullptr, nullptr, CM, CE, CE);
}

// round 8
// speedup vs baseline: 2.7738x; 1.0299x over previous
#include <cuda_runtime.h>
#include <cuda_bf16.h>
#include <math.h>
#include <stdint.h>

#define CB 2
#define CS 2048
#define CE 1024
#define CH 16
#define CD 64
#define CM (CB*CS)          // 4096 tokens
#define YAT_EPS 1e-5f

__device__ __forceinline__ uint32_t smem_u32(const void* p) {
    uint32_t a;
    asm("{ .reg .u64 t; cvta.to.shared.u64 t, %1; cvt.u32.u64 %0, t; }" : "=r"(a) : "l"(p));
    return a;
}

// ---- mma.sync / ldmatrix / cp.async helpers (portable to non-'a' sm_103) ----
__device__ __forceinline__ void ldsm_x4(uint32_t* r, uint32_t addr) {
    asm volatile("ldmatrix.sync.aligned.m8n8.x4.shared.b16 {%0,%1,%2,%3}, [%4];"
        : "=r"(r[0]), "=r"(r[1]), "=r"(r[2]), "=r"(r[3]) : "r"(addr));
}
__device__ __forceinline__ void ldsm_x4_t(uint32_t* r, uint32_t addr) {
    asm volatile("ldmatrix.sync.aligned.m8n8.x4.trans.shared.b16 {%0,%1,%2,%3}, [%4];"
        : "=r"(r[0]), "=r"(r[1]), "=r"(r[2]), "=r"(r[3]) : "r"(addr));
}
__device__ __forceinline__ void mma_bf16(float* c, const uint32_t* a, const uint32_t* b) {
    asm volatile(
        "mma.sync.aligned.m16n8k16.row.col.f32.bf16.bf16.f32 "
        "{%0,%1,%2,%3}, {%4,%5,%6,%7}, {%8,%9}, {%0,%1,%2,%3};"
        : "+f"(c[0]), "+f"(c[1]), "+f"(c[2]), "+f"(c[3])
        : "r"(a[0]), "r"(a[1]), "r"(a[2]), "r"(a[3]), "r"(b[0]), "r"(b[1]));
}
__device__ __forceinline__ uint32_t prmt7632(uint32_t a, uint32_t b) {
    uint32_t r; asm("prmt.b32 %0, %1, %2, 0x7632;" : "=r"(r) : "r"(a), "r"(b)); return r;
}
__device__ __forceinline__ uint32_t pkbf16x2(float lo, float hi) {
    uint32_t r; asm("cvt.rn.bf16x2.f32 %0, %1, %2;" : "=r"(r) : "f"(hi), "f"(lo)); return r;
}
__device__ __forceinline__ void cpasync16(uint32_t dst, const void* src) {
    asm volatile("cp.async.cg.shared.global [%0], [%1], 16;" :: "r"(dst), "l"(src));
}
#define CP_COMMIT() asm volatile("cp.async.commit_group;" ::: "memory")
#define CP_WAIT(n)  asm volatile("cp.async.wait_group %0;" :: "n"(n) : "memory")

// ---- Scratch (__device__ globals; allocation-free rule) ----
__device__ __nv_bfloat16 g_xh[(size_t)CM*CE], g_xl[(size_t)CM*CE];
__device__ __nv_bfloat16 g_oh[(size_t)CM*CE], g_ol[(size_t)CM*CE];
__device__ __nv_bfloat16 g_wqh[(size_t)CE*CE], g_wql[(size_t)CE*CE];
__device__ __nv_bfloat16 g_wkh[(size_t)CE*CE], g_wkl[(size_t)CE*CE];
__device__ __nv_bfloat16 g_wvh[(size_t)CE*CE], g_wvl[(size_t)CE*CE];
__device__ __nv_bfloat16 g_woh[(size_t)CE*CE], g_wol[(size_t)CE*CE];
__device__ __nv_bfloat16 g_aqh[(size_t)CM*CE], g_aql[(size_t)CM*CE];
__device__ __nv_bfloat16 g_akh[(size_t)CM*CE], g_akl[(size_t)CM*CE];
__device__ __nv_bfloat16 g_avh[(size_t)CM*CE], g_avl[(size_t)CM*CE];
__device__ float g_qn[(size_t)CH*CM];
__device__ float g_kn[(size_t)CH*CM];

// ---------------------------------------------------------------------------
// fp32 -> (bf16 hi, bf16 lo) split; batched over up to 4 arrays via blockIdx.y
// ---------------------------------------------------------------------------
struct SplitJob { const float* x; __nv_bfloat16* hi; __nv_bfloat16* lo; };

__global__ __launch_bounds__(256) void split_bf16_multi(
    SplitJob j0, SplitJob j1, SplitJob j2, SplitJob j3, int n4)
{
    int i = blockIdx.x * blockDim.x + threadIdx.x;
    if (i >= n4) return;
    SplitJob j = (blockIdx.y == 0) ? j0 : (blockIdx.y == 1) ? j1 : (blockIdx.y == 2) ? j2 : j3;
    float4 v = ((const float4*)j.x)[i];
    union { __nv_bfloat16 b[4]; uint2 u; } H, L;
    float a[4] = {v.x, v.y, v.z, v.w};
#pragma unroll
    for (int jj = 0; jj < 4; jj++) {
        __nv_bfloat16 h = __float2bfloat16(a[jj]);
        H.b[jj] = h;
        L.b[jj] = __float2bfloat16(a[jj] - __bfloat162float(h));
    }
    ((uint2*)j.hi)[i] = H.u;
    ((uint2*)j.lo)[i] = L.u;
}

// ---------------------------------------------------------------------------
// per-(token, head) squared norms from hi/lo pairs (y: 0=q, 1=k)
// ---------------------------------------------------------------------------
__global__ __launch_bounds__(256) void head_norms_hl2(
    const __nv_bfloat16* __restrict__ qhi, const __nv_bfloat16* __restrict__ qlo,
    const __nv_bfloat16* __restrict__ khi, const __nv_bfloat16* __restrict__ klo,
    float* __restrict__ qout, float* __restrict__ kout)
{
    const __nv_bfloat16* hi = blockIdx.y ? khi : qhi;
    const __nv_bfloat16* lo = blockIdx.y ? klo : qlo;
    float* out = blockIdx.y ? kout : qout;
    int tok = blockIdx.x * 16 + (threadIdx.x >> 4);
    int h = threadIdx.x & 15;
    size_t base = (size_t)tok * CE + h * CD;
    float s = 0.0f;
#pragma unroll
    for (int i = 0; i < 8; i++) {
        union { uint4 u; __nv_bfloat16 b[8]; } H, L;
        H.u = *(const uint4*)&hi[base + i * 8];
        L.u = *(const uint4*)&lo[base + i * 8];
#pragma unroll
        for (int j = 0; j < 8; j++) {
            float f = __bfloat162float(H.b[j]) + __bfloat162float(L.b[j]);
            s += f * f;
        }
    }
    out[(size_t)h * CM + tok] = s;
}

// ---------------------------------------------------------------------------
// C = A @ B^T + bias via mma.sync bf16 3-split; 2-stage cp.async pipeline
// with ONE barrier per iteration (prefetch issued post-barrier).
// Multi-job: blockIdx.z selects job (QKV fused in one launch).
// ---------------------------------------------------------------------------
#define LDA 40
#define STB (128*LDA*2)          // bytes per array per stage = 10240
#define HG_SMEM (2*4*STB)        // 81920 B

struct GemmJob {
    const __nv_bfloat16 *Ah, *Al, *Bh, *Bl;
    const float* bias;
    float* C;
    __nv_bfloat16 *Chi, *Clo;
};

__global__ __launch_bounds__(256) void hgemm_nt_3split(
    GemmJob j0, GemmJob j1, GemmJob j2, int M, int N, int K)
{
    extern __shared__ __nv_bfloat16 smem[];
    const uint32_t uS = smem_u32(smem);
    const GemmJob jb = (blockIdx.z == 0) ? j0 : (blockIdx.z == 1) ? j1 : j2;

    const int tid = threadIdx.x, lane = tid & 31, wid = tid >> 5;
    const int wm = wid >> 2, wn = wid & 3;
    const int row0 = blockIdx.y * 128, col0 = blockIdx.x * 128;

    float acc[4][4][4];
#pragma unroll
    for (int i = 0; i < 4; i++)
#pragma unroll
        for (int j = 0; j < 4; j++)
#pragma unroll
            for (int f = 0; f < 4; f++) acc[i][j][f] = 0.0f;

    const int a_row = lane & 15, a_kg = lane >> 4;
    const int b_row = ((lane >> 4) & 1) * 8 + (lane & 7);
    const int b_kg  = (lane >> 3) & 1;

    const int gr = tid >> 2;
    const int gc = (tid & 3) * 8;

    const int NT = K / 32;

    auto load_st = [&](int s, int t) {
        const int k0 = t * 32;
        const uint32_t sbase = uS + s * 4 * STB;
#pragma unroll
        for (int pp = 0; pp < 2; pp++) {
            int r = pp * 64 + gr;
            uint32_t doff = (uint32_t)(r * LDA + gc) * 2;
            size_t ga = (size_t)(row0 + r) * K + k0 + gc;
            size_t gb = (size_t)(col0 + r) * K + k0 + gc;
            cpasync16(sbase + 0 * STB + doff, &jb.Ah[ga]);
            cpasync16(sbase + 1 * STB + doff, &jb.Al[ga]);
            cpasync16(sbase + 2 * STB + doff, &jb.Bh[gb]);
            cpasync16(sbase + 3 * STB + doff, &jb.Bl[gb]);
        }
    };

    load_st(0, 0);
    CP_COMMIT();

    for (int t = 0; t < NT; t++) {
        CP_WAIT(0);          // stage t data landed (all groups done)
        __syncthreads();     // publish stage t; also: compute(t-1) on other buf done
        if (t + 1 < NT) {
            load_st((t + 1) & 1, t + 1);   // into buf last computed at t-1 — safe post-barrier
            CP_COMMIT();
        }

        const uint32_t sA_h = uS + ((t & 1) * 4 + 0) * STB;
        const uint32_t sA_l = uS + ((t & 1) * 4 + 1) * STB;
        const uint32_t sB_h = uS + ((t & 1) * 4 + 2) * STB;
        const uint32_t sB_l = uS + ((t & 1) * 4 + 3) * STB;

#pragma unroll
        for (int kk = 0; kk < 2; kk++) {
            const uint32_t aoff = ((wm * 64 + a_row) * LDA + kk * 16 + a_kg * 8) * 2;
            const uint32_t boff0 = ((wn * 32 + b_row) * LDA + kk * 16 + b_kg * 8) * 2;
            const uint32_t boff1 = boff0 + 16 * LDA * 2;

            uint32_t bh_f[4][2], bl_f[4][2], af[4][4];
            {
                uint32_t tt[4];
                ldsm_x4(tt, sB_h + boff0);
                bh_f[0][0] = tt[0]; bh_f[0][1] = tt[1]; bh_f[1][0] = tt[2]; bh_f[1][1] = tt[3];
                ldsm_x4(tt, sB_h + boff1);
                bh_f[2][0] = tt[0]; bh_f[2][1] = tt[1]; bh_f[3][0] = tt[2]; bh_f[3][1] = tt[3];
                ldsm_x4(tt, sB_l + boff0);
                bl_f[0][0] = tt[0]; bl_f[0][1] = tt[1]; bl_f[1][0] = tt[2]; bl_f[1][1] = tt[3];
                ldsm_x4(tt, sB_l + boff1);
                bl_f[2][0] = tt[0]; bl_f[2][1] = tt[1]; bl_f[3][0] = tt[2]; bl_f[3][1] = tt[3];
            }
#pragma unroll
            for (int mi = 0; mi < 4; mi++)
                ldsm_x4(af[mi], sA_h + aoff + mi * 16 * LDA * 2);
#pragma unroll
            for (int mi = 0; mi < 4; mi++)
#pragma unroll
                for (int ni = 0; ni < 4; ni++) {
                    mma_bf16(acc[mi][ni], af[mi], bh_f[ni]);
                    mma_bf16(acc[mi][ni], af[mi], bl_f[ni]);
                }
#pragma unroll
            for (int mi = 0; mi < 4; mi++)
                ldsm_x4(af[mi], sA_l + aoff + mi * 16 * LDA * 2);
#pragma unroll
            for (int mi = 0; mi < 4; mi++)
#pragma unroll
                for (int ni = 0; ni < 4; ni++)
                    mma_bf16(acc[mi][ni], af[mi], bh_f[ni]);
        }
        __syncthreads();     // compute(t) done before next iter's prefetch targets this buf
    }

    const int erow = lane >> 2, ecol = (lane & 3) * 2;
#pragma unroll
    for (int mi = 0; mi < 4; mi++) {
#pragma unroll
        for (int ni = 0; ni < 4; ni++) {
            int rg = row0 + wm * 64 + mi * 16 + erow;
            int cg = col0 + wn * 32 + ni * 8 + ecol;
            float2 bb = *(const float2*)&jb.bias[cg];
            float o00 = acc[mi][ni][0] + bb.x, o01 = acc[mi][ni][1] + bb.y;
            float o10 = acc[mi][ni][2] + bb.x, o11 = acc[mi][ni][3] + bb.y;
            size_t i0 = (size_t)rg * N + cg, i1 = (size_t)(rg + 8) * N + cg;
            if (jb.C) {
                *(float2*)&jb.C[i0] = make_float2(o00, o01);
                *(float2*)&jb.C[i1] = make_float2(o10, o11);
            }
            if (jb.Chi) {
                __nv_bfloat16 h00 = __float2bfloat16(o00), h01 = __float2bfloat16(o01);
                __nv_bfloat16 h10 = __float2bfloat16(o10), h11 = __float2bfloat16(o11);
                *(__nv_bfloat162*)&jb.Chi[i0] = __nv_bfloat162(h00, h01);
                *(__nv_bfloat162*)&jb.Chi[i1] = __nv_bfloat162(h10, h11);
                *(__nv_bfloat162*)&jb.Clo[i0] = __nv_bfloat162(
                    __float2bfloat16(o00 - __bfloat162float(h00)),
                    __float2bfloat16(o01 - __bfloat162float(h01)));
                *(__nv_bfloat162*)&jb.Clo[i1] = __nv_bfloat162(
                    __float2bfloat16(o10 - __bfloat162float(h10)),
                    __float2bfloat16(o11 - __bfloat162float(h11)));
            }
        }
    }
}

// ---------------------------------------------------------------------------
// YAT flash attention via mma.sync bf16 3-split (unchanged math, R6/R7 layout)
// ---------------------------------------------------------------------------
#define LDS 72
#define OQH 0
#define OQL 9216
#define OKH 18432
#define OKL 23040
#define OVH 27648
#define OVL 32256
#define ATTN_SMEM (36864*2 + 256)

__global__ __launch_bounds__(256) void yat_attn_mma(
    const __nv_bfloat16* __restrict__ Qhm, const __nv_bfloat16* __restrict__ Qlm,
    const __nv_bfloat16* __restrict__ Khm, const __nv_bfloat16* __restrict__ Klm,
    const __nv_bfloat16* __restrict__ Vhm, const __nv_bfloat16* __restrict__ Vlm,
    const float* __restrict__ qn, const float* __restrict__ kn,
    __nv_bfloat16* __restrict__ Ohm, __nv_bfloat16* __restrict__ Olm,
    const float* __restrict__ alphap)
{
    extern __shared__ __nv_bfloat16 sb[];
    __nv_bfloat16* sQh = sb + OQH;
    __nv_bfloat16* sQl = sb + OQL;
    __nv_bfloat16* sKh = sb + OKH;
    __nv_bfloat16* sKl = sb + OKL;
    __nv_bfloat16* sVh = sb + OVH;
    __nv_bfloat16* sVl = sb + OVL;
    float* skn = (float*)(sb + 36864);

    const int tid = threadIdx.x, lane = tid & 31, w = tid >> 5;
    const int g = lane >> 2, tg = lane & 3;
    const int b = blockIdx.z, h = blockIdx.y;
    const int q0 = blockIdx.x * 128;
    const size_t tokq = (size_t)b * CS + q0;

    const float scale = powf(8.0f / logf(65.0f), alphap[0]);

    {
        int c8 = tid & 7;
        int rb = tid >> 3;
#pragma unroll
        for (int i = 0; i < 4; i++) {
            int r = rb + i * 32;
            size_t gq = (tokq + r) * CE + h * CD + c8 * 8;
            *(uint4*)&sQh[r * LDS + c8 * 8] = *(const uint4*)&Qhm[gq];
            *(uint4*)&sQl[r * LDS + c8 * 8] = *(const uint4*)&Qlm[gq];
        }
    }

    const float sq0 = qn[(size_t)h * CM + tokq + w * 16 + g];
    const float sq1 = qn[(size_t)h * CM + tokq + w * 16 + g + 8];

    float m0 = -INFINITY, m1 = -INFINITY, l0 = 0.0f, l1 = 0.0f;
    float accO[8][4];
#pragma unroll
    for (int i = 0; i < 8; i++)
#pragma unroll
        for (int j = 0; j < 4; j++) accO[i][j] = 0.0f;

    const uint32_t uQh = smem_u32(sQh), uQl = smem_u32(sQl);
    const uint32_t uKh = smem_u32(sKh), uKl = smem_u32(sKl);
    const uint32_t uVh = smem_u32(sVh), uVl = smem_u32(sVl);

    const int a_row = lane & 15, a_kg = lane >> 4;
    const int b_row = ((lane >> 4) & 1) * 8 + (lane & 7);
    const int b_kg  = (lane >> 3) & 1;

    for (int t = 0; t < CS / 64; t++) {
        __syncthreads();
        {
            int r = tid >> 2, c8 = (tid & 3) * 2;
            size_t gk = ((size_t)b * CS + t * 64 + r) * CE + h * CD;
#pragma unroll
            for (int u = 0; u < 2; u++) {
                int cc = (c8 + u) * 8;
                *(uint4*)&sKh[r * LDS + cc] = *(const uint4*)&Khm[gk + cc];
                *(uint4*)&sKl[r * LDS + cc] = *(const uint4*)&Klm[gk + cc];
                *(uint4*)&sVh[r * LDS + cc] = *(const uint4*)&Vhm[gk + cc];
                *(uint4*)&sVl[r * LDS + cc] = *(const uint4*)&Vlm[gk + cc];
            }
        }
        if (tid < 64) skn[tid] = kn[(size_t)h * CM + b * CS + t * 64 + tid];
        __syncthreads();

        float sS[8][4];
#pragma unroll
        for (int i = 0; i < 8; i++)
#pragma unroll
            for (int j = 0; j < 4; j++) sS[i][j] = 0.0f;

#pragma unroll
        for (int kk = 0; kk < 4; kk++) {
            const uint32_t aoff = ((w * 16 + a_row) * LDS + kk * 16 + a_kg * 8) * 2;
            uint32_t ah[4], al[4];
            ldsm_x4(ah, uQh + aoff);
            ldsm_x4(al, uQl + aoff);
#pragma unroll
            for (int nb = 0; nb < 4; nb++) {
                const uint32_t boff = ((nb * 16 + b_row) * LDS + kk * 16 + b_kg * 8) * 2;
                uint32_t th[4], tl[4];
                ldsm_x4(th, uKh + boff);
                ldsm_x4(tl, uKl + boff);
                mma_bf16(sS[2 * nb], ah, th);
                mma_bf16(sS[2 * nb], ah, tl);
                mma_bf16(sS[2 * nb], al, th);
                mma_bf16(sS[2 * nb + 1], ah, th + 2);
                mma_bf16(sS[2 * nb + 1], ah, tl + 2);
                mma_bf16(sS[2 * nb + 1], al, th + 2);
            }
        }

        float mx0 = -INFINITY, mx1 = -INFINITY;
#pragma unroll
        for (int ni = 0; ni < 8; ni++) {
            int col = ni * 8 + tg * 2;
            float k0 = skn[col], k1 = skn[col + 1];
            float qk, d, s;
            qk = sS[ni][0]; d = sq0 + k0 - 2.0f * qk + YAT_EPS; s = scale * qk * qk / d;
            sS[ni][0] = s; mx0 = fmaxf(mx0, s);
            qk = sS[ni][1]; d = sq0 + k1 - 2.0f * qk + YAT_EPS; s = scale * qk * qk / d;
            sS[ni][1] = s; mx0 = fmaxf(mx0, s);
            qk = sS[ni][2]; d = sq1 + k0 - 2.0f * qk + YAT_EPS; s = scale * qk * qk / d;
            sS[ni][2] = s; mx1 = fmaxf(mx1, s);
            qk = sS[ni][3]; d = sq1 + k1 - 2.0f * qk + YAT_EPS; s = scale * qk * qk / d;
            sS[ni][3] = s; mx1 = fmaxf(mx1, s);
        }
#pragma unroll
        for (int off = 1; off <= 2; off <<= 1) {
            mx0 = fmaxf(mx0, __shfl_xor_sync(0xffffffffu, mx0, off));
            mx1 = fmaxf(mx1, __shfl_xor_sync(0xffffffffu, mx1, off));
        }
        float nm0 = fmaxf(m0, mx0), nm1 = fmaxf(m1, mx1);
        float corr0 = __expf(m0 - nm0), corr1 = __expf(m1 - nm1);
        m0 = nm0; m1 = nm1;
        float rs0 = 0.0f, rs1 = 0.0f;
#pragma unroll
        for (int ni = 0; ni < 8; ni++) {
            sS[ni][0] = __expf(sS[ni][0] - nm0); rs0 += sS[ni][0];
            sS[ni][1] = __expf(sS[ni][1] - nm0); rs0 += sS[ni][1];
            sS[ni][2] = __expf(sS[ni][2] - nm1); rs1 += sS[ni][2];
            sS[ni][3] = __expf(sS[ni][3] - nm1); rs1 += sS[ni][3];
        }
#pragma unroll
        for (int off = 1; off <= 2; off <<= 1) {
            rs0 += __shfl_xor_sync(0xffffffffu, rs0, off);
            rs1 += __shfl_xor_sync(0xffffffffu, rs1, off);
        }
        l0 = l0 * corr0 + rs0;
        l1 = l1 * corr1 + rs1;
#pragma unroll
        for (int ni = 0; ni < 8; ni++) {
            accO[ni][0] *= corr0; accO[ni][1] *= corr0;
            accO[ni][2] *= corr1; accO[ni][3] *= corr1;
        }

#pragma unroll
        for (int kk = 0; kk < 4; kk++) {
            const float* e = sS[2 * kk];
            const float* f = sS[2 * kk + 1];
            uint32_t ph[4], pl[4];
            {
                uint32_t u0, u1;
                float h0, h1;
                u0 = __float_as_uint(e[0]); u1 = __float_as_uint(e[1]);
                ph[0] = prmt7632(u0, u1);
                h0 = __uint_as_float(u0 & 0xffff0000u); h1 = __uint_as_float(u1 & 0xffff0000u);
                pl[0] = pkbf16x2(e[0] - h0, e[1] - h1);
                u0 = __float_as_uint(e[2]); u1 = __float_as_uint(e[3]);
                ph[1] = prmt7632(u0, u1);
                h0 = __uint_as_float(u0 & 0xffff0000u); h1 = __uint_as_float(u1 & 0xffff0000u);
                pl[1] = pkbf16x2(e[2] - h0, e[3] - h1);
                u0 = __float_as_uint(f[0]); u1 = __float_as_uint(f[1]);
                ph[2] = prmt7632(u0, u1);
                h0 = __uint_as_float(u0 & 0xffff0000u); h1 = __uint_as_float(u1 & 0xffff0000u);
                pl[2] = pkbf16x2(f[0] - h0, f[1] - h1);
                u0 = __float_as_uint(f[2]); u1 = __float_as_uint(f[3]);
                ph[3] = prmt7632(u0, u1);
                h0 = __uint_as_float(u0 & 0xffff0000u); h1 = __uint_as_float(u1 & 0xffff0000u);
                pl[3] = pkbf16x2(f[2] - h0, f[3] - h1);
            }
#pragma unroll
            for (int db = 0; db < 4; db++) {
                const uint32_t voff = ((kk * 16 + (lane & 15)) * LDS + db * 16 + (lane >> 4) * 8) * 2;
                uint32_t th[4], tl[4];
                ldsm_x4_t(th, uVh + voff);
                ldsm_x4_t(tl, uVl + voff);
                mma_bf16(accO[2 * db], ph, th);
                mma_bf16(accO[2 * db], ph, tl);
                mma_bf16(accO[2 * db], pl, th);
                mma_bf16(accO[2 * db + 1], ph, th + 2);
                mma_bf16(accO[2 * db + 1], ph, tl + 2);
                mma_bf16(accO[2 * db + 1], pl, th + 2);
            }
        }
    }

    float inv0 = 1.0f / l0, inv1 = 1.0f / l1;
    size_t ro = (tokq + w * 16 + g) * CE + h * CD;
#pragma unroll
    for (int ni = 0; ni < 8; ni++) {
        int c = ni * 8 + tg * 2;
        float o00 = accO[ni][0] * inv0, o01 = accO[ni][1] * inv0;
        float o10 = accO[ni][2] * inv1, o11 = accO[ni][3] * inv1;
        __nv_bfloat16 h00 = __float2bfloat16(o00), h01 = __float2bfloat16(o01);
        __nv_bfloat16 h10 = __float2bfloat16(o10), h11 = __float2bfloat16(o11);
        *(__nv_bfloat162*)&Ohm[ro + c] = __nv_bfloat162(h00, h01);
        *(__nv_bfloat162*)&Ohm[ro + 8 * CE + c] = __nv_bfloat162(h10, h11);
        *(__nv_bfloat162*)&Olm[ro + c] = __nv_bfloat162(
            __float2bfloat16(o00 - __bfloat162float(h00)),
            __float2bfloat16(o01 - __bfloat162float(h01)));
        *(__nv_bfloat162*)&Olm[ro + 8 * CE + c] = __nv_bfloat162(
            __float2bfloat16(o10 - __bfloat162float(h10)),
            __float2bfloat16(o11 - __bfloat162float(h11)));
    }
}

// ---------------------------------------------------------------------------
extern "C" void kernel_launch(void* const* d_in, const int* in_sizes, int n_in,
                              void* d_out, int out_size)
{
    (void)in_sizes; (void)n_in; (void)out_size;
    const float* query = (const float*)d_in[0];
    const float* Wq    = (const float*)d_in[1];
    const float* bq    = (const float*)d_in[2];
    const float* Wk    = (const float*)d_in[3];
    const float* bk    = (const float*)d_in[4];
    const float* Wv    = (const float*)d_in[5];
    const float* bv    = (const float*)d_in[6];
    const float* Wo    = (const float*)d_in[7];
    const float* bo    = (const float*)d_in[8];
    const float* alpha = (const float*)d_in[9];

    float *qn, *kn;
    cudaGetSymbolAddress((void**)&qn, g_qn);
    cudaGetSymbolAddress((void**)&kn, g_kn);
    __nv_bfloat16 *xh, *xl, *oh, *ol, *wqh, *wql, *wkh, *wkl, *wvh, *wvl, *woh, *wol;
    __nv_bfloat16 *aqh, *aql, *akh, *akl, *avh, *avl;
    cudaGetSymbolAddress((void**)&xh, g_xh);   cudaGetSymbolAddress((void**)&xl, g_xl);
    cudaGetSymbolAddress((void**)&oh, g_oh);   cudaGetSymbolAddress((void**)&ol, g_ol);
    cudaGetSymbolAddress((void**)&wqh, g_wqh); cudaGetSymbolAddress((void**)&wql, g_wql);
    cudaGetSymbolAddress((void**)&wkh, g_wkh); cudaGetSymbolAddress((void**)&wkl, g_wkl);
    cudaGetSymbolAddress((void**)&wvh, g_wvh); cudaGetSymbolAddress((void**)&wvl, g_wvl);
    cudaGetSymbolAddress((void**)&woh, g_woh); cudaGetSymbolAddress((void**)&wol, g_wol);
    cudaGetSymbolAddress((void**)&aqh, g_aqh); cudaGetSymbolAddress((void**)&aql, g_aql);
    cudaGetSymbolAddress((void**)&akh, g_akh); cudaGetSymbolAddress((void**)&akl, g_akl);
    cudaGetSymbolAddress((void**)&avh, g_avh); cudaGetSymbolAddress((void**)&avl, g_avl);

    const int nx4 = CM * CE / 4;
    const int nw4 = CE * CE / 4;
    // x split (big) + 4 weight splits merged into one launch each
    {
        SplitJob jx = {query, xh, xl};
        split_bf16_multi<<<dim3(nx4 / 256, 1), 256>>>(jx, jx, jx, jx, nx4);
        SplitJob jq = {Wq, wqh, wql}, jk = {Wk, wkh, wkl}, jv = {Wv, wvh, wvl}, jo = {Wo, woh, wol};
        split_bf16_multi<<<dim3(nw4 / 256, 4), 256>>>(jq, jk, jv, jo, nw4);
    }

    cudaFuncSetAttribute(hgemm_nt_3split, cudaFuncAttributeMaxDynamicSharedMemorySize, HG_SMEM);
    // QKV fused: one launch, blockIdx.z = projection
    {
        GemmJob jq = {xh, xl, wqh, wql, bq, nullptr, aqh, aql};
        GemmJob jk = {xh, xl, wkh, wkl, bk, nullptr, akh, akl};
        GemmJob jv = {xh, xl, wvh, wvl, bv, nullptr, avh, avl};
        hgemm_nt_3split<<<dim3(CE / 128, CM / 128, 3), 256, HG_SMEM>>>(jq, jk, jv, CM, CE, CE);
    }

    head_norms_hl2<<<dim3(CM / 16, 2), 256>>>(aqh, aql, akh, akl, qn, kn);

    cudaFuncSetAttribute(yat_attn_mma, cudaFuncAttributeMaxDynamicSharedMemorySize, ATTN_SMEM);
    yat_attn_mma<<<dim3(CS / 128, CH, CB), 256, ATTN_SMEM>>>(
        aqh, aql, akh, akl, avh, avl, qn, kn, oh, ol, alpha);

    // output projection
    {
        GemmJob jo = {oh, ol, woh, wol, bo, (float*)d_out, nullptr, nullptr};
        hgemm_nt_3split<<<dim3(CE / 128, CM / 128, 1), 256, HG_SMEM>>>(jo, jo, jo, CM, CE, CE);
    }
}

// round 9
// speedup vs baseline: 2.7900x; 1.0058x over previous
#include <cuda_runtime.h>
#include <cuda_bf16.h>
#include <math.h>
#include <stdint.h>

#define CB 2
#define CS 2048
#define CE 1024
#define CH 16
#define CD 64
#define CM (CB*CS)          // 4096 tokens
#define YAT_EPS 1e-5f

__device__ __forceinline__ uint32_t smem_u32(const void* p) {
    uint32_t a;
    asm("{ .reg .u64 t; cvta.to.shared.u64 t, %1; cvt.u32.u64 %0, t; }" : "=r"(a) : "l"(p));
    return a;
}

// ---- mma.sync / ldmatrix / cp.async helpers (portable to non-'a' sm_103) ----
__device__ __forceinline__ void ldsm_x4(uint32_t* r, uint32_t addr) {
    asm volatile("ldmatrix.sync.aligned.m8n8.x4.shared.b16 {%0,%1,%2,%3}, [%4];"
        : "=r"(r[0]), "=r"(r[1]), "=r"(r[2]), "=r"(r[3]) : "r"(addr));
}
__device__ __forceinline__ void ldsm_x4_t(uint32_t* r, uint32_t addr) {
    asm volatile("ldmatrix.sync.aligned.m8n8.x4.trans.shared.b16 {%0,%1,%2,%3}, [%4];"
        : "=r"(r[0]), "=r"(r[1]), "=r"(r[2]), "=r"(r[3]) : "r"(addr));
}
__device__ __forceinline__ void mma_bf16(float* c, const uint32_t* a, const uint32_t* b) {
    asm volatile(
        "mma.sync.aligned.m16n8k16.row.col.f32.bf16.bf16.f32 "
        "{%0,%1,%2,%3}, {%4,%5,%6,%7}, {%8,%9}, {%0,%1,%2,%3};"
        : "+f"(c[0]), "+f"(c[1]), "+f"(c[2]), "+f"(c[3])
        : "r"(a[0]), "r"(a[1]), "r"(a[2]), "r"(a[3]), "r"(b[0]), "r"(b[1]));
}
__device__ __forceinline__ uint32_t prmt7632(uint32_t a, uint32_t b) {
    uint32_t r; asm("prmt.b32 %0, %1, %2, 0x7632;" : "=r"(r) : "r"(a), "r"(b)); return r;
}
__device__ __forceinline__ uint32_t pkbf16x2(float lo, float hi) {
    uint32_t r; asm("cvt.rn.bf16x2.f32 %0, %1, %2;" : "=r"(r) : "f"(hi), "f"(lo)); return r;
}
__device__ __forceinline__ void cpasync16(uint32_t dst, const void* src) {
    asm volatile("cp.async.cg.shared.global [%0], [%1], 16;" :: "r"(dst), "l"(src));
}
#define CP_COMMIT() asm volatile("cp.async.commit_group;" ::: "memory")
#define CP_WAIT(n)  asm volatile("cp.async.wait_group %0;" :: "n"(n) : "memory")

// ---- Scratch (__device__ globals; allocation-free rule) ----
__device__ __nv_bfloat16 g_xh[(size_t)CM*CE], g_xl[(size_t)CM*CE];
__device__ __nv_bfloat16 g_oh[(size_t)CM*CE], g_ol[(size_t)CM*CE];
__device__ __nv_bfloat16 g_wqh[(size_t)CE*CE], g_wql[(size_t)CE*CE];
__device__ __nv_bfloat16 g_wkh[(size_t)CE*CE], g_wkl[(size_t)CE*CE];
__device__ __nv_bfloat16 g_wvh[(size_t)CE*CE], g_wvl[(size_t)CE*CE];
__device__ __nv_bfloat16 g_woh[(size_t)CE*CE], g_wol[(size_t)CE*CE];
__device__ __nv_bfloat16 g_aqh[(size_t)CM*CE], g_aql[(size_t)CM*CE];
__device__ __nv_bfloat16 g_akh[(size_t)CM*CE], g_akl[(size_t)CM*CE];
__device__ __nv_bfloat16 g_avh[(size_t)CM*CE], g_avl[(size_t)CM*CE];
__device__ float g_qn[(size_t)CH*CM];
__device__ float g_kn[(size_t)CH*CM];

// ---------------------------------------------------------------------------
__global__ __launch_bounds__(256) void zero_norms(float* qn, float* kn)
{
    int i = blockIdx.x * blockDim.x + threadIdx.x;
    qn[i] = 0.0f; kn[i] = 0.0f;
}

// ---------------------------------------------------------------------------
// fp32 -> (bf16 hi, bf16 lo) split; batched over up to 4 arrays via blockIdx.y
// ---------------------------------------------------------------------------
struct SplitJob { const float* x; __nv_bfloat16* hi; __nv_bfloat16* lo; };

__global__ __launch_bounds__(256) void split_bf16_multi(
    SplitJob j0, SplitJob j1, SplitJob j2, SplitJob j3, int n4)
{
    int i = blockIdx.x * blockDim.x + threadIdx.x;
    if (i >= n4) return;
    SplitJob j = (blockIdx.y == 0) ? j0 : (blockIdx.y == 1) ? j1 : (blockIdx.y == 2) ? j2 : j3;
    float4 v = ((const float4*)j.x)[i];
    union { __nv_bfloat16 b[4]; uint2 u; } H, L;
    float a[4] = {v.x, v.y, v.z, v.w};
#pragma unroll
    for (int jj = 0; jj < 4; jj++) {
        __nv_bfloat16 h = __float2bfloat16(a[jj]);
        H.b[jj] = h;
        L.b[jj] = __float2bfloat16(a[jj] - __bfloat162float(h));
    }
    ((uint2*)j.hi)[i] = H.u;
    ((uint2*)j.lo)[i] = L.u;
}

// ---------------------------------------------------------------------------
// C = A @ B^T + bias via mma.sync bf16 3-split; 2-stage cp.async pipeline,
// single barrier per iteration. Optional fused head-norm accumulation.
// Multi-job: blockIdx.z selects job (QKV fused in one launch).
// ---------------------------------------------------------------------------
#define LDA 40
#define STB (128*LDA*2)          // bytes per array per stage = 10240
#define HG_SMEM (2*4*STB)        // 81920 B

struct GemmJob {
    const __nv_bfloat16 *Ah, *Al, *Bh, *Bl;
    const float* bias;
    float* C;
    __nv_bfloat16 *Chi, *Clo;
    float* norm;                 // if non-null: atomicAdd per-(head,row) sum of squares
};

__global__ __launch_bounds__(256) void hgemm_nt_3split(
    GemmJob j0, GemmJob j1, GemmJob j2, int M, int N, int K)
{
    extern __shared__ __nv_bfloat16 smem[];
    const uint32_t uS = smem_u32(smem);
    const GemmJob jb = (blockIdx.z == 0) ? j0 : (blockIdx.z == 1) ? j1 : j2;

    const int tid = threadIdx.x, lane = tid & 31, wid = tid >> 5;
    const int wm = wid >> 2, wn = wid & 3;
    const int row0 = blockIdx.y * 128, col0 = blockIdx.x * 128;

    float acc[4][4][4];
#pragma unroll
    for (int i = 0; i < 4; i++)
#pragma unroll
        for (int j = 0; j < 4; j++)
#pragma unroll
            for (int f = 0; f < 4; f++) acc[i][j][f] = 0.0f;

    const int a_row = lane & 15, a_kg = lane >> 4;
    const int b_row = ((lane >> 4) & 1) * 8 + (lane & 7);
    const int b_kg  = (lane >> 3) & 1;

    const int gr = tid >> 2;
    const int gc = (tid & 3) * 8;

    const int NT = K / 32;

    auto load_st = [&](int s, int t) {
        const int k0 = t * 32;
        const uint32_t sbase = uS + s * 4 * STB;
#pragma unroll
        for (int pp = 0; pp < 2; pp++) {
            int r = pp * 64 + gr;
            uint32_t doff = (uint32_t)(r * LDA + gc) * 2;
            size_t ga = (size_t)(row0 + r) * K + k0 + gc;
            size_t gb = (size_t)(col0 + r) * K + k0 + gc;
            cpasync16(sbase + 0 * STB + doff, &jb.Ah[ga]);
            cpasync16(sbase + 1 * STB + doff, &jb.Al[ga]);
            cpasync16(sbase + 2 * STB + doff, &jb.Bh[gb]);
            cpasync16(sbase + 3 * STB + doff, &jb.Bl[gb]);
        }
    };

    load_st(0, 0);
    CP_COMMIT();

    for (int t = 0; t < NT; t++) {
        CP_WAIT(0);          // this thread's copies for stage t done
        __syncthreads();     // publish stage t; all warps finished compute(t-1)
        if (t + 1 < NT) {
            load_st((t + 1) & 1, t + 1);   // target buf computed at t-1 — safe
            CP_COMMIT();
        }

        const uint32_t sA_h = uS + ((t & 1) * 4 + 0) * STB;
        const uint32_t sA_l = uS + ((t & 1) * 4 + 1) * STB;
        const uint32_t sB_h = uS + ((t & 1) * 4 + 2) * STB;
        const uint32_t sB_l = uS + ((t & 1) * 4 + 3) * STB;

#pragma unroll
        for (int kk = 0; kk < 2; kk++) {
            const uint32_t aoff = ((wm * 64 + a_row) * LDA + kk * 16 + a_kg * 8) * 2;
            const uint32_t boff0 = ((wn * 32 + b_row) * LDA + kk * 16 + b_kg * 8) * 2;
            const uint32_t boff1 = boff0 + 16 * LDA * 2;

            uint32_t bh_f[4][2], bl_f[4][2], af[4][4];
            {
                uint32_t tt[4];
                ldsm_x4(tt, sB_h + boff0);
                bh_f[0][0] = tt[0]; bh_f[0][1] = tt[1]; bh_f[1][0] = tt[2]; bh_f[1][1] = tt[3];
                ldsm_x4(tt, sB_h + boff1);
                bh_f[2][0] = tt[0]; bh_f[2][1] = tt[1]; bh_f[3][0] = tt[2]; bh_f[3][1] = tt[3];
                ldsm_x4(tt, sB_l + boff0);
                bl_f[0][0] = tt[0]; bl_f[0][1] = tt[1]; bl_f[1][0] = tt[2]; bl_f[1][1] = tt[3];
                ldsm_x4(tt, sB_l + boff1);
                bl_f[2][0] = tt[0]; bl_f[2][1] = tt[1]; bl_f[3][0] = tt[2]; bl_f[3][1] = tt[3];
            }
#pragma unroll
            for (int mi = 0; mi < 4; mi++)
                ldsm_x4(af[mi], sA_h + aoff + mi * 16 * LDA * 2);
#pragma unroll
            for (int mi = 0; mi < 4; mi++)
#pragma unroll
                for (int ni = 0; ni < 4; ni++) {
                    mma_bf16(acc[mi][ni], af[mi], bh_f[ni]);
                    mma_bf16(acc[mi][ni], af[mi], bl_f[ni]);
                }
#pragma unroll
            for (int mi = 0; mi < 4; mi++)
                ldsm_x4(af[mi], sA_l + aoff + mi * 16 * LDA * 2);
#pragma unroll
            for (int mi = 0; mi < 4; mi++)
#pragma unroll
                for (int ni = 0; ni < 4; ni++)
                    mma_bf16(acc[mi][ni], af[mi], bh_f[ni]);
        }
        // no trailing barrier: next iter's barrier orders reuse
    }
    __syncthreads();   // last compute done before epilogue (paranoia vs nothing after)

    const int erow = lane >> 2, ecol = (lane & 3) * 2;
    const int hh = (col0 + wn * 32) >> 6;   // all this thread's columns in one head
#pragma unroll
    for (int mi = 0; mi < 4; mi++) {
        float s0 = 0.0f, s1 = 0.0f;
#pragma unroll
        for (int ni = 0; ni < 4; ni++) {
            int rg = row0 + wm * 64 + mi * 16 + erow;
            int cg = col0 + wn * 32 + ni * 8 + ecol;
            float2 bb = *(const float2*)&jb.bias[cg];
            float o00 = acc[mi][ni][0] + bb.x, o01 = acc[mi][ni][1] + bb.y;
            float o10 = acc[mi][ni][2] + bb.x, o11 = acc[mi][ni][3] + bb.y;
            s0 += o00 * o00 + o01 * o01;
            s1 += o10 * o10 + o11 * o11;
            size_t i0 = (size_t)rg * N + cg, i1 = (size_t)(rg + 8) * N + cg;
            if (jb.C) {
                *(float2*)&jb.C[i0] = make_float2(o00, o01);
                *(float2*)&jb.C[i1] = make_float2(o10, o11);
            }
            if (jb.Chi) {
                __nv_bfloat16 h00 = __float2bfloat16(o00), h01 = __float2bfloat16(o01);
                __nv_bfloat16 h10 = __float2bfloat16(o10), h11 = __float2bfloat16(o11);
                *(__nv_bfloat162*)&jb.Chi[i0] = __nv_bfloat162(h00, h01);
                *(__nv_bfloat162*)&jb.Chi[i1] = __nv_bfloat162(h10, h11);
                *(__nv_bfloat162*)&jb.Clo[i0] = __nv_bfloat162(
                    __float2bfloat16(o00 - __bfloat162float(h00)),
                    __float2bfloat16(o01 - __bfloat162float(h01)));
                *(__nv_bfloat162*)&jb.Clo[i1] = __nv_bfloat162(
                    __float2bfloat16(o10 - __bfloat162float(h10)),
                    __float2bfloat16(o11 - __bfloat162float(h11)));
            }
        }
        if (jb.norm) {
            int rg = row0 + wm * 64 + mi * 16 + erow;
            atomicAdd(&jb.norm[(size_t)hh * CM + rg], s0);
            atomicAdd(&jb.norm[(size_t)hh * CM + rg + 8], s1);
        }
    }
}

// ---------------------------------------------------------------------------
// YAT flash attention via mma.sync bf16 3-split, cp.async double-buffered K/V.
// ---------------------------------------------------------------------------
#define LDS 72
// element offsets: Qh 0, Ql 9216; KV stages at 18432 (4608 el per sub-array)
#define KVST_EL 18432
#define ATTN_SMEM (55296*2 + 512 + 128)   // 111232 B

__global__ void __launch_bounds__(256, 2) yat_attn_mma(
    const __nv_bfloat16* __restrict__ Qhm, const __nv_bfloat16* __restrict__ Qlm,
    const __nv_bfloat16* __restrict__ Khm, const __nv_bfloat16* __restrict__ Klm,
    const __nv_bfloat16* __restrict__ Vhm, const __nv_bfloat16* __restrict__ Vlm,
    const float* __restrict__ qn, const float* __restrict__ kn,
    __nv_bfloat16* __restrict__ Ohm, __nv_bfloat16* __restrict__ Olm,
    const float* __restrict__ alphap)
{
    extern __shared__ __nv_bfloat16 sb[];
    const uint32_t uS = smem_u32(sb);
    const uint32_t uQh = uS, uQl = uS + 9216 * 2;
    const uint32_t uKV = uS + KVST_EL * 2;          // stage area base (bytes)
    const uint32_t uKN = uS + 55296 * 2;            // kn stage area

    const int tid = threadIdx.x, lane = tid & 31, w = tid >> 5;
    const int g = lane >> 2, tg = lane & 3;
    const int b = blockIdx.z, h = blockIdx.y;
    const int q0 = blockIdx.x * 128;
    const size_t tokq = (size_t)b * CS + q0;

    const float scale = powf(8.0f / logf(65.0f), alphap[0]);

    // persistent Q hi/lo tile (128 x 64)
    {
        int c8 = tid & 7;
        int rb = tid >> 3;
#pragma unroll
        for (int i = 0; i < 4; i++) {
            int r = rb + i * 32;
            size_t gq = (tokq + r) * CE + h * CD + c8 * 8;
            *(uint4*)&sb[r * LDS + c8 * 8] = *(const uint4*)&Qhm[gq];
            *(uint4*)&sb[9216 + r * LDS + c8 * 8] = *(const uint4*)&Qlm[gq];
        }
    }

    const float sq0 = qn[(size_t)h * CM + tokq + w * 16 + g];
    const float sq1 = qn[(size_t)h * CM + tokq + w * 16 + g + 8];

    float m0 = -INFINITY, m1 = -INFINITY, l0 = 0.0f, l1 = 0.0f;
    float accO[8][4];
#pragma unroll
    for (int i = 0; i < 8; i++)
#pragma unroll
        for (int j = 0; j < 4; j++) accO[i][j] = 0.0f;

    const int a_row = lane & 15, a_kg = lane >> 4;
    const int b_row = ((lane >> 4) & 1) * 8 + (lane & 7);
    const int b_kg  = (lane >> 3) & 1;

    auto load_kv = [&](int stg, int t) {
        int r = tid >> 2, c2 = (tid & 3) * 2;
        size_t gk = ((size_t)b * CS + t * 64 + r) * CE + h * CD;
        const uint32_t sbase = uKV + (uint32_t)stg * 18432u * 2u;
#pragma unroll
        for (int u = 0; u < 2; u++) {
            int cc = (c2 + u) * 8;
            uint32_t doff = (uint32_t)(r * LDS + cc) * 2;
            cpasync16(sbase + 0u * 9216u + doff, &Khm[gk + cc]);
            cpasync16(sbase + 1u * 9216u + doff, &Klm[gk + cc]);
            cpasync16(sbase + 2u * 9216u + doff, &Vhm[gk + cc]);
            cpasync16(sbase + 3u * 9216u + doff, &Vlm[gk + cc]);
        }
        if (tid < 16)
            cpasync16(uKN + (uint32_t)stg * 256u + tid * 16,
                      &kn[(size_t)h * CM + b * CS + t * 64 + tid * 4]);
    };

    load_kv(0, 0);
    CP_COMMIT();

    const int NT = CS / 64;
    for (int t = 0; t < NT; t++) {
        CP_WAIT(0);
        __syncthreads();                 // publish stage t; all warps done with t-1
        if (t + 1 < NT) {
            load_kv((t + 1) & 1, t + 1);
            CP_COMMIT();
        }
        const uint32_t kb = uKV + (uint32_t)(t & 1) * 18432u * 2u;
        const uint32_t uKh = kb, uKl = kb + 9216u, uVh = kb + 18432u, uVl = kb + 27648u;
        const float* skn = (const float*)((const char*)sb + (55296 * 2) + (t & 1) * 256);

        float sS[8][4];
#pragma unroll
        for (int i = 0; i < 8; i++)
#pragma unroll
            for (int j = 0; j < 4; j++) sS[i][j] = 0.0f;

#pragma unroll
        for (int kk = 0; kk < 4; kk++) {
            const uint32_t aoff = ((w * 16 + a_row) * LDS + kk * 16 + a_kg * 8) * 2;
            uint32_t ah[4], al[4];
            ldsm_x4(ah, uQh + aoff);
            ldsm_x4(al, uQl + aoff);
#pragma unroll
            for (int nb = 0; nb < 4; nb++) {
                const uint32_t boff = ((nb * 16 + b_row) * LDS + kk * 16 + b_kg * 8) * 2;
                uint32_t th[4], tl[4];
                ldsm_x4(th, uKh + boff);
                ldsm_x4(tl, uKl + boff);
                mma_bf16(sS[2 * nb], ah, th);
                mma_bf16(sS[2 * nb], ah, tl);
                mma_bf16(sS[2 * nb], al, th);
                mma_bf16(sS[2 * nb + 1], ah, th + 2);
                mma_bf16(sS[2 * nb + 1], ah, tl + 2);
                mma_bf16(sS[2 * nb + 1], al, th + 2);
            }
        }

        float mx0 = -INFINITY, mx1 = -INFINITY;
#pragma unroll
        for (int ni = 0; ni < 8; ni++) {
            int col = ni * 8 + tg * 2;
            float k0 = skn[col], k1 = skn[col + 1];
            float qk, d, s;
            qk = sS[ni][0]; d = sq0 + k0 - 2.0f * qk + YAT_EPS; s = scale * qk * qk / d;
            sS[ni][0] = s; mx0 = fmaxf(mx0, s);
            qk = sS[ni][1]; d = sq0 + k1 - 2.0f * qk + YAT_EPS; s = scale * qk * qk / d;
            sS[ni][1] = s; mx0 = fmaxf(mx0, s);
            qk = sS[ni][2]; d = sq1 + k0 - 2.0f * qk + YAT_EPS; s = scale * qk * qk / d;
            sS[ni][2] = s; mx1 = fmaxf(mx1, s);
            qk = sS[ni][3]; d = sq1 + k1 - 2.0f * qk + YAT_EPS; s = scale * qk * qk / d;
            sS[ni][3] = s; mx1 = fmaxf(mx1, s);
        }
#pragma unroll
        for (int off = 1; off <= 2; off <<= 1) {
            mx0 = fmaxf(mx0, __shfl_xor_sync(0xffffffffu, mx0, off));
            mx1 = fmaxf(mx1, __shfl_xor_sync(0xffffffffu, mx1, off));
        }
        float nm0 = fmaxf(m0, mx0), nm1 = fmaxf(m1, mx1);
        float corr0 = __expf(m0 - nm0), corr1 = __expf(m1 - nm1);
        m0 = nm0; m1 = nm1;
        float rs0 = 0.0f, rs1 = 0.0f;
#pragma unroll
        for (int ni = 0; ni < 8; ni++) {
            sS[ni][0] = __expf(sS[ni][0] - nm0); rs0 += sS[ni][0];
            sS[ni][1] = __expf(sS[ni][1] - nm0); rs0 += sS[ni][1];
            sS[ni][2] = __expf(sS[ni][2] - nm1); rs1 += sS[ni][2];
            sS[ni][3] = __expf(sS[ni][3] - nm1); rs1 += sS[ni][3];
        }
#pragma unroll
        for (int off = 1; off <= 2; off <<= 1) {
            rs0 += __shfl_xor_sync(0xffffffffu, rs0, off);
            rs1 += __shfl_xor_sync(0xffffffffu, rs1, off);
        }
        l0 = l0 * corr0 + rs0;
        l1 = l1 * corr1 + rs1;
#pragma unroll
        for (int ni = 0; ni < 8; ni++) {
            accO[ni][0] *= corr0; accO[ni][1] *= corr0;
            accO[ni][2] *= corr1; accO[ni][3] *= corr1;
        }

#pragma unroll
        for (int kk = 0; kk < 4; kk++) {
            const float* e = sS[2 * kk];
            const float* f = sS[2 * kk + 1];
            uint32_t ph[4], pl[4];
            {
                uint32_t u0, u1;
                float h0, h1;
                u0 = __float_as_uint(e[0]); u1 = __float_as_uint(e[1]);
                ph[0] = prmt7632(u0, u1);
                h0 = __uint_as_float(u0 & 0xffff0000u); h1 = __uint_as_float(u1 & 0xffff0000u);
                pl[0] = pkbf16x2(e[0] - h0, e[1] - h1);
                u0 = __float_as_uint(e[2]); u1 = __float_as_uint(e[3]);
                ph[1] = prmt7632(u0, u1);
                h0 = __uint_as_float(u0 & 0xffff0000u); h1 = __uint_as_float(u1 & 0xffff0000u);
                pl[1] = pkbf16x2(e[2] - h0, e[3] - h1);
                u0 = __float_as_uint(f[0]); u1 = __float_as_uint(f[1]);
                ph[2] = prmt7632(u0, u1);
                h0 = __uint_as_float(u0 & 0xffff0000u); h1 = __uint_as_float(u1 & 0xffff0000u);
                pl[2] = pkbf16x2(f[0] - h0, f[1] - h1);
                u0 = __float_as_uint(f[2]); u1 = __float_as_uint(f[3]);
                ph[3] = prmt7632(u0, u1);
                h0 = __uint_as_float(u0 & 0xffff0000u); h1 = __uint_as_float(u1 & 0xffff0000u);
                pl[3] = pkbf16x2(f[2] - h0, f[3] - h1);
            }
#pragma unroll
            for (int db = 0; db < 4; db++) {
                const uint32_t voff = ((kk * 16 + (lane & 15)) * LDS + db * 16 + (lane >> 4) * 8) * 2;
                uint32_t th[4], tl[4];
                ldsm_x4_t(th, uVh + voff);
                ldsm_x4_t(tl, uVl + voff);
                mma_bf16(accO[2 * db], ph, th);
                mma_bf16(accO[2 * db], ph, tl);
                mma_bf16(accO[2 * db], pl, th);
                mma_bf16(accO[2 * db + 1], ph, th + 2);
                mma_bf16(accO[2 * db + 1], ph, tl + 2);
                mma_bf16(accO[2 * db + 1], pl, th + 2);
            }
        }
    }

    float inv0 = 1.0f / l0, inv1 = 1.0f / l1;
    size_t ro = (tokq + w * 16 + g) * CE + h * CD;
#pragma unroll
    for (int ni = 0; ni < 8; ni++) {
        int c = ni * 8 + tg * 2;
        float o00 = accO[ni][0] * inv0, o01 = accO[ni][1] * inv0;
        float o10 = accO[ni][2] * inv1, o11 = accO[ni][3] * inv1;
        __nv_bfloat16 h00 = __float2bfloat16(o00), h01 = __float2bfloat16(o01);
        __nv_bfloat16 h10 = __float2bfloat16(o10), h11 = __float2bfloat16(o11);
        *(__nv_bfloat162*)&Ohm[ro + c] = __nv_bfloat162(h00, h01);
        *(__nv_bfloat162*)&Ohm[ro + 8 * CE + c] = __nv_bfloat162(h10, h11);
        *(__nv_bfloat162*)&Olm[ro + c] = __nv_bfloat162(
            __float2bfloat16(o00 - __bfloat162float(h00)),
            __float2bfloat16(o01 - __bfloat162float(h01)));
        *(__nv_bfloat162*)&Olm[ro + 8 * CE + c] = __nv_bfloat162(
            __float2bfloat16(o10 - __bfloat162float(h10)),
            __float2bfloat16(o11 - __bfloat162float(h11)));
    }
}

// ---------------------------------------------------------------------------
extern "C" void kernel_launch(void* const* d_in, const int* in_sizes, int n_in,
                              void* d_out, int out_size)
{
    (void)in_sizes; (void)n_in; (void)out_size;
    const float* query = (const float*)d_in[0];
    const float* Wq    = (const float*)d_in[1];
    const float* bq    = (const float*)d_in[2];
    const float* Wk    = (const float*)d_in[3];
    const float* bk    = (const float*)d_in[4];
    const float* Wv    = (const float*)d_in[5];
    const float* bv    = (const float*)d_in[6];
    const float* Wo    = (const float*)d_in[7];
    const float* bo    = (const float*)d_in[8];
    const float* alpha = (const float*)d_in[9];

    float *qn, *kn;
    cudaGetSymbolAddress((void**)&qn, g_qn);
    cudaGetSymbolAddress((void**)&kn, g_kn);
    __nv_bfloat16 *xh, *xl, *oh, *ol, *wqh, *wql, *wkh, *wkl, *wvh, *wvl, *woh, *wol;
    __nv_bfloat16 *aqh, *aql, *akh, *akl, *avh, *avl;
    cudaGetSymbolAddress((void**)&xh, g_xh);   cudaGetSymbolAddress((void**)&xl, g_xl);
    cudaGetSymbolAddress((void**)&oh, g_oh);   cudaGetSymbolAddress((void**)&ol, g_ol);
    cudaGetSymbolAddress((void**)&wqh, g_wqh); cudaGetSymbolAddress((void**)&wql, g_wql);
    cudaGetSymbolAddress((void**)&wkh, g_wkh); cudaGetSymbolAddress((void**)&wkl, g_wkl);
    cudaGetSymbolAddress((void**)&wvh, g_wvh); cudaGetSymbolAddress((void**)&wvl, g_wvl);
    cudaGetSymbolAddress((void**)&woh, g_woh); cudaGetSymbolAddress((void**)&wol, g_wol);
    cudaGetSymbolAddress((void**)&aqh, g_aqh); cudaGetSymbolAddress((void**)&aql, g_aql);
    cudaGetSymbolAddress((void**)&akh, g_akh); cudaGetSymbolAddress((void**)&akl, g_akl);
    cudaGetSymbolAddress((void**)&avh, g_avh); cudaGetSymbolAddress((void**)&avl, g_avl);

    const int nx4 = CM * CE / 4;
    const int nw4 = CE * CE / 4;
    zero_norms<<<CH * CM / 256, 256>>>(qn, kn);
    {
        SplitJob jx = {query, xh, xl};
        split_bf16_multi<<<dim3(nx4 / 256, 1), 256>>>(jx, jx, jx, jx, nx4);
        SplitJob jq = {Wq, wqh, wql}, jk = {Wk, wkh, wkl}, jv = {Wv, wvh, wvl}, jo = {Wo, woh, wol};
        split_bf16_multi<<<dim3(nw4 / 256, 4), 256>>>(jq, jk, jv, jo, nw4);
    }

    cudaFuncSetAttribute(hgemm_nt_3split, cudaFuncAttributeMaxDynamicSharedMemorySize, HG_SMEM);
    {
        GemmJob jq = {xh, xl, wqh, wql, bq, nullptr, aqh, aql, qn};
        GemmJob jk = {xh, xl, wkh, wkl, bk, nullptr, akh, akl, kn};
        GemmJob jv = {xh, xl, wvh, wvl, bv, nullptr, avh, avl, nullptr};
        hgemm_nt_3split<<<dim3(CE / 128, CM / 128, 3), 256, HG_SMEM>>>(jq, jk, jv, CM, CE, CE);
    }

    cudaFuncSetAttribute(yat_attn_mma, cudaFuncAttributeMaxDynamicSharedMemorySize, ATTN_SMEM);
    yat_attn_mma<<<dim3(CS / 128, CH, CB), 256, ATTN_SMEM>>>(
        aqh, aql, akh, akl, avh, avl, qn, kn, oh, ol, alpha);

    {
        GemmJob jo = {oh, ol, woh, wol, bo, (float*)d_out, nullptr, nullptr, nullptr};
        hgemm_nt_3split<<<dim3(CE / 128, CM / 128, 1), 256, HG_SMEM>>>(jo, jo, jo, CM, CE, CE);
    }
}

// round 10
// speedup vs baseline: 3.0585x; 1.0963x over previous
#include <cuda_runtime.h>
#include <cuda_bf16.h>
#include <math.h>
#include <stdint.h>

#define CB 2
#define CS 2048
#define CE 1024
#define CH 16
#define CD 64
#define CM (CB*CS)          // 4096 tokens
#define YAT_EPS 1e-5f

__device__ __forceinline__ uint32_t smem_u32(const void* p) {
    uint32_t a;
    asm("{ .reg .u64 t; cvta.to.shared.u64 t, %1; cvt.u32.u64 %0, t; }" : "=r"(a) : "l"(p));
    return a;
}

// ---- mma.sync / ldmatrix / cp.async helpers (portable to non-'a' sm_103) ----
__device__ __forceinline__ void ldsm_x4(uint32_t* r, uint32_t addr) {
    asm volatile("ldmatrix.sync.aligned.m8n8.x4.shared.b16 {%0,%1,%2,%3}, [%4];"
        : "=r"(r[0]), "=r"(r[1]), "=r"(r[2]), "=r"(r[3]) : "r"(addr));
}
__device__ __forceinline__ void ldsm_x4_t(uint32_t* r, uint32_t addr) {
    asm volatile("ldmatrix.sync.aligned.m8n8.x4.trans.shared.b16 {%0,%1,%2,%3}, [%4];"
        : "=r"(r[0]), "=r"(r[1]), "=r"(r[2]), "=r"(r[3]) : "r"(addr));
}
__device__ __forceinline__ void mma_bf16(float* c, const uint32_t* a, const uint32_t* b) {
    asm volatile(
        "mma.sync.aligned.m16n8k16.row.col.f32.bf16.bf16.f32 "
        "{%0,%1,%2,%3}, {%4,%5,%6,%7}, {%8,%9}, {%0,%1,%2,%3};"
        : "+f"(c[0]), "+f"(c[1]), "+f"(c[2]), "+f"(c[3])
        : "r"(a[0]), "r"(a[1]), "r"(a[2]), "r"(a[3]), "r"(b[0]), "r"(b[1]));
}
__device__ __forceinline__ uint32_t prmt7632(uint32_t a, uint32_t b) {
    uint32_t r; asm("prmt.b32 %0, %1, %2, 0x7632;" : "=r"(r) : "r"(a), "r"(b)); return r;
}
__device__ __forceinline__ uint32_t pkbf16x2(float lo, float hi) {
    uint32_t r; asm("cvt.rn.bf16x2.f32 %0, %1, %2;" : "=r"(r) : "f"(hi), "f"(lo)); return r;
}
__device__ __forceinline__ void cpasync16(uint32_t dst, const void* src) {
    asm volatile("cp.async.cg.shared.global [%0], [%1], 16;" :: "r"(dst), "l"(src));
}
#define CP_COMMIT() asm volatile("cp.async.commit_group;" ::: "memory")
#define CP_WAIT(n)  asm volatile("cp.async.wait_group %0;" :: "n"(n) : "memory")

// ---- Scratch (__device__ globals; allocation-free rule) ----
__device__ __nv_bfloat16 g_xh[(size_t)CM*CE], g_xl[(size_t)CM*CE];
__device__ __nv_bfloat16 g_oh[(size_t)CM*CE], g_ol[(size_t)CM*CE];
__device__ __nv_bfloat16 g_wqh[(size_t)CE*CE], g_wql[(size_t)CE*CE];
__device__ __nv_bfloat16 g_wkh[(size_t)CE*CE], g_wkl[(size_t)CE*CE];
__device__ __nv_bfloat16 g_wvh[(size_t)CE*CE], g_wvl[(size_t)CE*CE];
__device__ __nv_bfloat16 g_woh[(size_t)CE*CE], g_wol[(size_t)CE*CE];
__device__ __nv_bfloat16 g_aqh[(size_t)CM*CE], g_aql[(size_t)CM*CE];
__device__ __nv_bfloat16 g_akh[(size_t)CM*CE], g_akl[(size_t)CM*CE];
__device__ __nv_bfloat16 g_avh[(size_t)CM*CE], g_avl[(size_t)CM*CE];
__device__ float g_qn[(size_t)CH*CM];
__device__ float g_kn[(size_t)CH*CM];

// ---------------------------------------------------------------------------
__global__ __launch_bounds__(256) void zero_norms(float* qn, float* kn)
{
    int i = blockIdx.x * blockDim.x + threadIdx.x;
    qn[i] = 0.0f; kn[i] = 0.0f;
}

// ---------------------------------------------------------------------------
struct SplitJob { const float* x; __nv_bfloat16* hi; __nv_bfloat16* lo; };

__global__ __launch_bounds__(256) void split_bf16_multi(
    SplitJob j0, SplitJob j1, SplitJob j2, SplitJob j3, int n4)
{
    int i = blockIdx.x * blockDim.x + threadIdx.x;
    if (i >= n4) return;
    SplitJob j = (blockIdx.y == 0) ? j0 : (blockIdx.y == 1) ? j1 : (blockIdx.y == 2) ? j2 : j3;
    float4 v = ((const float4*)j.x)[i];
    union { __nv_bfloat16 b[4]; uint2 u; } H, L;
    float a[4] = {v.x, v.y, v.z, v.w};
#pragma unroll
    for (int jj = 0; jj < 4; jj++) {
        __nv_bfloat16 h = __float2bfloat16(a[jj]);
        H.b[jj] = h;
        L.b[jj] = __float2bfloat16(a[jj] - __bfloat162float(h));
    }
    ((uint2*)j.hi)[i] = H.u;
    ((uint2*)j.lo)[i] = L.u;
}

// ---------------------------------------------------------------------------
// C = A @ B^T + bias via mma.sync bf16 3-split (unchanged from R9).
// ---------------------------------------------------------------------------
#define LDA 40
#define STB (128*LDA*2)
#define HG_SMEM (2*4*STB)

struct GemmJob {
    const __nv_bfloat16 *Ah, *Al, *Bh, *Bl;
    const float* bias;
    float* C;
    __nv_bfloat16 *Chi, *Clo;
    float* norm;
};

__global__ __launch_bounds__(256) void hgemm_nt_3split(
    GemmJob j0, GemmJob j1, GemmJob j2, int M, int N, int K)
{
    extern __shared__ __nv_bfloat16 smem[];
    const uint32_t uS = smem_u32(smem);
    const GemmJob jb = (blockIdx.z == 0) ? j0 : (blockIdx.z == 1) ? j1 : j2;

    const int tid = threadIdx.x, lane = tid & 31, wid = tid >> 5;
    const int wm = wid >> 2, wn = wid & 3;
    const int row0 = blockIdx.y * 128, col0 = blockIdx.x * 128;

    float acc[4][4][4];
#pragma unroll
    for (int i = 0; i < 4; i++)
#pragma unroll
        for (int j = 0; j < 4; j++)
#pragma unroll
            for (int f = 0; f < 4; f++) acc[i][j][f] = 0.0f;

    const int a_row = lane & 15, a_kg = lane >> 4;
    const int b_row = ((lane >> 4) & 1) * 8 + (lane & 7);
    const int b_kg  = (lane >> 3) & 1;

    const int gr = tid >> 2;
    const int gc = (tid & 3) * 8;

    const int NT = K / 32;

    auto load_st = [&](int s, int t) {
        const int k0 = t * 32;
        const uint32_t sbase = uS + s * 4 * STB;
#pragma unroll
        for (int pp = 0; pp < 2; pp++) {
            int r = pp * 64 + gr;
            uint32_t doff = (uint32_t)(r * LDA + gc) * 2;
            size_t ga = (size_t)(row0 + r) * K + k0 + gc;
            size_t gb = (size_t)(col0 + r) * K + k0 + gc;
            cpasync16(sbase + 0 * STB + doff, &jb.Ah[ga]);
            cpasync16(sbase + 1 * STB + doff, &jb.Al[ga]);
            cpasync16(sbase + 2 * STB + doff, &jb.Bh[gb]);
            cpasync16(sbase + 3 * STB + doff, &jb.Bl[gb]);
        }
    };

    load_st(0, 0);
    CP_COMMIT();

    for (int t = 0; t < NT; t++) {
        CP_WAIT(0);
        __syncthreads();
        if (t + 1 < NT) {
            load_st((t + 1) & 1, t + 1);
            CP_COMMIT();
        }

        const uint32_t sA_h = uS + ((t & 1) * 4 + 0) * STB;
        const uint32_t sA_l = uS + ((t & 1) * 4 + 1) * STB;
        const uint32_t sB_h = uS + ((t & 1) * 4 + 2) * STB;
        const uint32_t sB_l = uS + ((t & 1) * 4 + 3) * STB;

#pragma unroll
        for (int kk = 0; kk < 2; kk++) {
            const uint32_t aoff = ((wm * 64 + a_row) * LDA + kk * 16 + a_kg * 8) * 2;
            const uint32_t boff0 = ((wn * 32 + b_row) * LDA + kk * 16 + b_kg * 8) * 2;
            const uint32_t boff1 = boff0 + 16 * LDA * 2;

            uint32_t bh_f[4][2], bl_f[4][2], af[4][4];
            {
                uint32_t tt[4];
                ldsm_x4(tt, sB_h + boff0);
                bh_f[0][0] = tt[0]; bh_f[0][1] = tt[1]; bh_f[1][0] = tt[2]; bh_f[1][1] = tt[3];
                ldsm_x4(tt, sB_h + boff1);
                bh_f[2][0] = tt[0]; bh_f[2][1] = tt[1]; bh_f[3][0] = tt[2]; bh_f[3][1] = tt[3];
                ldsm_x4(tt, sB_l + boff0);
                bl_f[0][0] = tt[0]; bl_f[0][1] = tt[1]; bl_f[1][0] = tt[2]; bl_f[1][1] = tt[3];
                ldsm_x4(tt, sB_l + boff1);
                bl_f[2][0] = tt[0]; bl_f[2][1] = tt[1]; bl_f[3][0] = tt[2]; bl_f[3][1] = tt[3];
            }
#pragma unroll
            for (int mi = 0; mi < 4; mi++)
                ldsm_x4(af[mi], sA_h + aoff + mi * 16 * LDA * 2);
#pragma unroll
            for (int mi = 0; mi < 4; mi++)
#pragma unroll
                for (int ni = 0; ni < 4; ni++) {
                    mma_bf16(acc[mi][ni], af[mi], bh_f[ni]);
                    mma_bf16(acc[mi][ni], af[mi], bl_f[ni]);
                }
#pragma unroll
            for (int mi = 0; mi < 4; mi++)
                ldsm_x4(af[mi], sA_l + aoff + mi * 16 * LDA * 2);
#pragma unroll
            for (int mi = 0; mi < 4; mi++)
#pragma unroll
                for (int ni = 0; ni < 4; ni++)
                    mma_bf16(acc[mi][ni], af[mi], bh_f[ni]);
        }
    }
    __syncthreads();

    const int erow = lane >> 2, ecol = (lane & 3) * 2;
    const int hh = (col0 + wn * 32) >> 6;
#pragma unroll
    for (int mi = 0; mi < 4; mi++) {
        float s0 = 0.0f, s1 = 0.0f;
#pragma unroll
        for (int ni = 0; ni < 4; ni++) {
            int rg = row0 + wm * 64 + mi * 16 + erow;
            int cg = col0 + wn * 32 + ni * 8 + ecol;
            float2 bb = *(const float2*)&jb.bias[cg];
            float o00 = acc[mi][ni][0] + bb.x, o01 = acc[mi][ni][1] + bb.y;
            float o10 = acc[mi][ni][2] + bb.x, o11 = acc[mi][ni][3] + bb.y;
            s0 += o00 * o00 + o01 * o01;
            s1 += o10 * o10 + o11 * o11;
            size_t i0 = (size_t)rg * N + cg, i1 = (size_t)(rg + 8) * N + cg;
            if (jb.C) {
                *(float2*)&jb.C[i0] = make_float2(o00, o01);
                *(float2*)&jb.C[i1] = make_float2(o10, o11);
            }
            if (jb.Chi) {
                __nv_bfloat16 h00 = __float2bfloat16(o00), h01 = __float2bfloat16(o01);
                __nv_bfloat16 h10 = __float2bfloat16(o10), h11 = __float2bfloat16(o11);
                *(__nv_bfloat162*)&jb.Chi[i0] = __nv_bfloat162(h00, h01);
                *(__nv_bfloat162*)&jb.Chi[i1] = __nv_bfloat162(h10, h11);
                *(__nv_bfloat162*)&jb.Clo[i0] = __nv_bfloat162(
                    __float2bfloat16(o00 - __bfloat162float(h00)),
                    __float2bfloat16(o01 - __bfloat162float(h01)));
                *(__nv_bfloat162*)&jb.Clo[i1] = __nv_bfloat162(
                    __float2bfloat16(o10 - __bfloat162float(h10)),
                    __float2bfloat16(o11 - __bfloat162float(h11)));
            }
        }
        if (jb.norm) {
            int rg = row0 + wm * 64 + mi * 16 + erow;
            atomicAdd(&jb.norm[(size_t)hh * CM + rg], s0);
            atomicAdd(&jb.norm[(size_t)hh * CM + rg + 8], s1);
        }
    }
}

// ---------------------------------------------------------------------------
// YAT flash attention: no-max softmax (scores bounded; clamp@75 guard),
// MUFU-RCP division, deferred denominator reduction.
// ---------------------------------------------------------------------------
#define LDS 72
#define KVST_EL 18432
#define ATTN_SMEM (55296*2 + 512 + 128)

__global__ void __launch_bounds__(256, 2) yat_attn_mma(
    const __nv_bfloat16* __restrict__ Qhm, const __nv_bfloat16* __restrict__ Qlm,
    const __nv_bfloat16* __restrict__ Khm, const __nv_bfloat16* __restrict__ Klm,
    const __nv_bfloat16* __restrict__ Vhm, const __nv_bfloat16* __restrict__ Vlm,
    const float* __restrict__ qn, const float* __restrict__ kn,
    __nv_bfloat16* __restrict__ Ohm, __nv_bfloat16* __restrict__ Olm,
    const float* __restrict__ alphap)
{
    extern __shared__ __nv_bfloat16 sb[];
    const uint32_t uS = smem_u32(sb);
    const uint32_t uQh = uS, uQl = uS + 9216 * 2;
    const uint32_t uKV = uS + KVST_EL * 2;
    const uint32_t uKN = uS + 55296 * 2;

    const int tid = threadIdx.x, lane = tid & 31, w = tid >> 5;
    const int g = lane >> 2, tg = lane & 3;
    const int b = blockIdx.z, h = blockIdx.y;
    const int q0 = blockIdx.x * 128;
    const size_t tokq = (size_t)b * CS + q0;

    const float scale = powf(8.0f / logf(65.0f), alphap[0]);

    {
        int c8 = tid & 7;
        int rb = tid >> 3;
#pragma unroll
        for (int i = 0; i < 4; i++) {
            int r = rb + i * 32;
            size_t gq = (tokq + r) * CE + h * CD + c8 * 8;
            *(uint4*)&sb[r * LDS + c8 * 8] = *(const uint4*)&Qhm[gq];
            *(uint4*)&sb[9216 + r * LDS + c8 * 8] = *(const uint4*)&Qlm[gq];
        }
    }

    const float sq0 = qn[(size_t)h * CM + tokq + w * 16 + g];
    const float sq1 = qn[(size_t)h * CM + tokq + w * 16 + g + 8];

    float l0 = 0.0f, l1 = 0.0f;      // per-thread partial denominators
    float accO[8][4];
#pragma unroll
    for (int i = 0; i < 8; i++)
#pragma unroll
        for (int j = 0; j < 4; j++) accO[i][j] = 0.0f;

    const int a_row = lane & 15, a_kg = lane >> 4;
    const int b_row = ((lane >> 4) & 1) * 8 + (lane & 7);
    const int b_kg  = (lane >> 3) & 1;

    auto load_kv = [&](int stg, int t) {
        int r = tid >> 2, c2 = (tid & 3) * 2;
        size_t gk = ((size_t)b * CS + t * 64 + r) * CE + h * CD;
        const uint32_t sbase = uKV + (uint32_t)stg * 18432u * 2u;
#pragma unroll
        for (int u = 0; u < 2; u++) {
            int cc = (c2 + u) * 8;
            uint32_t doff = (uint32_t)(r * LDS + cc) * 2;
            cpasync16(sbase + 0u * 9216u + doff, &Khm[gk + cc]);
            cpasync16(sbase + 1u * 9216u + doff, &Klm[gk + cc]);
            cpasync16(sbase + 2u * 9216u + doff, &Vhm[gk + cc]);
            cpasync16(sbase + 3u * 9216u + doff, &Vlm[gk + cc]);
        }
        if (tid < 16)
            cpasync16(uKN + (uint32_t)stg * 256u + tid * 16,
                      &kn[(size_t)h * CM + b * CS + t * 64 + tid * 4]);
    };

    load_kv(0, 0);
    CP_COMMIT();

    const int NT = CS / 64;
    for (int t = 0; t < NT; t++) {
        CP_WAIT(0);
        __syncthreads();
        if (t + 1 < NT) {
            load_kv((t + 1) & 1, t + 1);
            CP_COMMIT();
        }
        const uint32_t kb = uKV + (uint32_t)(t & 1) * 18432u * 2u;
        const uint32_t uKh = kb, uKl = kb + 9216u, uVh = kb + 18432u, uVl = kb + 27648u;
        const float* skn = (const float*)((const char*)sb + (55296 * 2) + (t & 1) * 256);

        float sS[8][4];
#pragma unroll
        for (int i = 0; i < 8; i++)
#pragma unroll
            for (int j = 0; j < 4; j++) sS[i][j] = 0.0f;

#pragma unroll
        for (int kk = 0; kk < 4; kk++) {
            const uint32_t aoff = ((w * 16 + a_row) * LDS + kk * 16 + a_kg * 8) * 2;
            uint32_t ah[4], al[4];
            ldsm_x4(ah, uQh + aoff);
            ldsm_x4(al, uQl + aoff);
#pragma unroll
            for (int nb = 0; nb < 4; nb++) {
                const uint32_t boff = ((nb * 16 + b_row) * LDS + kk * 16 + b_kg * 8) * 2;
                uint32_t th[4], tl[4];
                ldsm_x4(th, uKh + boff);
                ldsm_x4(tl, uKl + boff);
                mma_bf16(sS[2 * nb], ah, th);
                mma_bf16(sS[2 * nb], ah, tl);
                mma_bf16(sS[2 * nb], al, th);
                mma_bf16(sS[2 * nb + 1], ah, th + 2);
                mma_bf16(sS[2 * nb + 1], ah, tl + 2);
                mma_bf16(sS[2 * nb + 1], al, th + 2);
            }
        }

        // YAT score -> exp (no max-shift; scores bounded, clamp@75 is a pure guard)
#pragma unroll
        for (int ni = 0; ni < 8; ni++) {
            int col = ni * 8 + tg * 2;
            float k0 = skn[col], k1 = skn[col + 1];
            float qk, d, s;
            qk = sS[ni][0]; d = sq0 + k0 - 2.0f * qk + YAT_EPS;
            s = fminf(scale * __fdividef(qk * qk, d), 75.0f);
            sS[ni][0] = __expf(s); l0 += sS[ni][0];
            qk = sS[ni][1]; d = sq0 + k1 - 2.0f * qk + YAT_EPS;
            s = fminf(scale * __fdividef(qk * qk, d), 75.0f);
            sS[ni][1] = __expf(s); l0 += sS[ni][1];
            qk = sS[ni][2]; d = sq1 + k0 - 2.0f * qk + YAT_EPS;
            s = fminf(scale * __fdividef(qk * qk, d), 75.0f);
            sS[ni][2] = __expf(s); l1 += sS[ni][2];
            qk = sS[ni][3]; d = sq1 + k1 - 2.0f * qk + YAT_EPS;
            s = fminf(scale * __fdividef(qk * qk, d), 75.0f);
            sS[ni][3] = __expf(s); l1 += sS[ni][3];
        }

        // O += P @ V (P hi/lo in registers)
#pragma unroll
        for (int kk = 0; kk < 4; kk++) {
            const float* e = sS[2 * kk];
            const float* f = sS[2 * kk + 1];
            uint32_t ph[4], pl[4];
            {
                uint32_t u0, u1;
                float h0, h1;
                u0 = __float_as_uint(e[0]); u1 = __float_as_uint(e[1]);
                ph[0] = prmt7632(u0, u1);
                h0 = __uint_as_float(u0 & 0xffff0000u); h1 = __uint_as_float(u1 & 0xffff0000u);
                pl[0] = pkbf16x2(e[0] - h0, e[1] - h1);
                u0 = __float_as_uint(e[2]); u1 = __float_as_uint(e[3]);
                ph[1] = prmt7632(u0, u1);
                h0 = __uint_as_float(u0 & 0xffff0000u); h1 = __uint_as_float(u1 & 0xffff0000u);
                pl[1] = pkbf16x2(e[2] - h0, e[3] - h1);
                u0 = __float_as_uint(f[0]); u1 = __float_as_uint(f[1]);
                ph[2] = prmt7632(u0, u1);
                h0 = __uint_as_float(u0 & 0xffff0000u); h1 = __uint_as_float(u1 & 0xffff0000u);
                pl[2] = pkbf16x2(f[0] - h0, f[1] - h1);
                u0 = __float_as_uint(f[2]); u1 = __float_as_uint(f[3]);
                ph[3] = prmt7632(u0, u1);
                h0 = __uint_as_float(u0 & 0xffff0000u); h1 = __uint_as_float(u1 & 0xffff0000u);
                pl[3] = pkbf16x2(f[2] - h0, f[3] - h1);
            }
#pragma unroll
            for (int db = 0; db < 4; db++) {
                const uint32_t voff = ((kk * 16 + (lane & 15)) * LDS + db * 16 + (lane >> 4) * 8) * 2;
                uint32_t th[4], tl[4];
                ldsm_x4_t(th, uVh + voff);
                ldsm_x4_t(tl, uVl + voff);
                mma_bf16(accO[2 * db], ph, th);
                mma_bf16(accO[2 * db], ph, tl);
                mma_bf16(accO[2 * db], pl, th);
                mma_bf16(accO[2 * db + 1], ph, th + 2);
                mma_bf16(accO[2 * db + 1], ph, tl + 2);
                mma_bf16(accO[2 * db + 1], pl, th + 2);
            }
        }
    }

    // single cross-lane denominator reduction (4-lane groups)
#pragma unroll
    for (int off = 1; off <= 2; off <<= 1) {
        l0 += __shfl_xor_sync(0xffffffffu, l0, off);
        l1 += __shfl_xor_sync(0xffffffffu, l1, off);
    }

    float inv0 = __fdividef(1.0f, l0), inv1 = __fdividef(1.0f, l1);
    size_t ro = (tokq + w * 16 + g) * CE + h * CD;
#pragma unroll
    for (int ni = 0; ni < 8; ni++) {
        int c = ni * 8 + tg * 2;
        float o00 = accO[ni][0] * inv0, o01 = accO[ni][1] * inv0;
        float o10 = accO[ni][2] * inv1, o11 = accO[ni][3] * inv1;
        __nv_bfloat16 h00 = __float2bfloat16(o00), h01 = __float2bfloat16(o01);
        __nv_bfloat16 h10 = __float2bfloat16(o10), h11 = __float2bfloat16(o11);
        *(__nv_bfloat162*)&Ohm[ro + c] = __nv_bfloat162(h00, h01);
        *(__nv_bfloat162*)&Ohm[ro + 8 * CE + c] = __nv_bfloat162(h10, h11);
        *(__nv_bfloat162*)&Olm[ro + c] = __nv_bfloat162(
            __float2bfloat16(o00 - __bfloat162float(h00)),
            __float2bfloat16(o01 - __bfloat162float(h01)));
        *(__nv_bfloat162*)&Olm[ro + 8 * CE + c] = __nv_bfloat162(
            __float2bfloat16(o10 - __bfloat162float(h10)),
            __float2bfloat16(o11 - __bfloat162float(h11)));
    }
}

// ---------------------------------------------------------------------------
extern "C" void kernel_launch(void* const* d_in, const int* in_sizes, int n_in,
                              void* d_out, int out_size)
{
    (void)in_sizes; (void)n_in; (void)out_size;
    const float* query = (const float*)d_in[0];
    const float* Wq    = (const float*)d_in[1];
    const float* bq    = (const float*)d_in[2];
    const float* Wk    = (const float*)d_in[3];
    const float* bk    = (const float*)d_in[4];
    const float* Wv    = (const float*)d_in[5];
    const float* bv    = (const float*)d_in[6];
    const float* Wo    = (const float*)d_in[7];
    const float* bo    = (const float*)d_in[8];
    const float* alpha = (const float*)d_in[9];

    float *qn, *kn;
    cudaGetSymbolAddress((void**)&qn, g_qn);
    cudaGetSymbolAddress((void**)&kn, g_kn);
    __nv_bfloat16 *xh, *xl, *oh, *ol, *wqh, *wql, *wkh, *wkl, *wvh, *wvl, *woh, *wol;
    __nv_bfloat16 *aqh, *aql, *akh, *akl, *avh, *avl;
    cudaGetSymbolAddress((void**)&xh, g_xh);   cudaGetSymbolAddress((void**)&xl, g_xl);
    cudaGetSymbolAddress((void**)&oh, g_oh);   cudaGetSymbolAddress((void**)&ol, g_ol);
    cudaGetSymbolAddress((void**)&wqh, g_wqh); cudaGetSymbolAddress((void**)&wql, g_wql);
    cudaGetSymbolAddress((void**)&wkh, g_wkh); cudaGetSymbolAddress((void**)&wkl, g_wkl);
    cudaGetSymbolAddress((void**)&wvh, g_wvh); cudaGetSymbolAddress((void**)&wvl, g_wvl);
    cudaGetSymbolAddress((void**)&woh, g_woh); cudaGetSymbolAddress((void**)&wol, g_wol);
    cudaGetSymbolAddress((void**)&aqh, g_aqh); cudaGetSymbolAddress((void**)&aql, g_aql);
    cudaGetSymbolAddress((void**)&akh, g_akh); cudaGetSymbolAddress((void**)&akl, g_akl);
    cudaGetSymbolAddress((void**)&avh, g_avh); cudaGetSymbolAddress((void**)&avl, g_avl);

    const int nx4 = CM * CE / 4;
    const int nw4 = CE * CE / 4;
    zero_norms<<<CH * CM / 256, 256>>>(qn, kn);
    {
        SplitJob jx = {query, xh, xl};
        split_bf16_multi<<<dim3(nx4 / 256, 1), 256>>>(jx, jx, jx, jx, nx4);
        SplitJob jq = {Wq, wqh, wql}, jk = {Wk, wkh, wkl}, jv = {Wv, wvh, wvl}, jo = {Wo, woh, wol};
        split_bf16_multi<<<dim3(nw4 / 256, 4), 256>>>(jq, jk, jv, jo, nw4);
    }

    cudaFuncSetAttribute(hgemm_nt_3split, cudaFuncAttributeMaxDynamicSharedMemorySize, HG_SMEM);
    {
        GemmJob jq = {xh, xl, wqh, wql, bq, nullptr, aqh, aql, qn};
        GemmJob jk = {xh, xl, wkh, wkl, bk, nullptr, akh, akl, kn};
        GemmJob jv = {xh, xl, wvh, wvl, bv, nullptr, avh, avl, nullptr};
        hgemm_nt_3split<<<dim3(CE / 128, CM / 128, 3), 256, HG_SMEM>>>(jq, jk, jv, CM, CE, CE);
    }

    cudaFuncSetAttribute(yat_attn_mma, cudaFuncAttributeMaxDynamicSharedMemorySize, ATTN_SMEM);
    yat_attn_mma<<<dim3(CS / 128, CH, CB), 256, ATTN_SMEM>>>(
        aqh, aql, akh, akl, avh, avl, qn, kn, oh, ol, alpha);

    {
        GemmJob jo = {oh, ol, woh, wol, bo, (float*)d_out, nullptr, nullptr, nullptr};
        hgemm_nt_3split<<<dim3(CE / 128, CM / 128, 1), 256, HG_SMEM>>>(jo, jo, jo, CM, CE, CE);
    }
}